// round 8
// baseline (speedup 1.0000x reference)
#include <cuda_runtime.h>
#include <cstdint>

#define BATCH 2
#define SEQ   2048
#define HID   1024
#define NHEAD 16
#define HDIM  64
#define NTOK  (BATCH*SEQ)

// Scratch (device globals: allocation-free rule)
__device__ float g_qkv[NTOK * 3 * HID];   // (B,S,3,NH,HD) tf32-rounded
__device__ float g_attn[NTOK * HID];      // tf32-rounded
__device__ float g_xc[NTOK * HID];
__device__ float g_w1[HID * 3 * HID];
__device__ float g_w2[HID * HID];

// ---------------------------------------------------------------------------
__device__ __forceinline__ float tf32f(float x) {
    uint32_t u;
    asm("cvt.rna.tf32.f32 %0, %1;" : "=r"(u) : "f"(x));
    return __uint_as_float(u);
}
__device__ __forceinline__ float ex2(float x) {
    float y;
    asm("ex2.approx.ftz.f32 %0, %1;" : "=f"(y) : "f"(x));
    return y;
}
__device__ __forceinline__ uint32_t fbits(float x) { return __float_as_uint(x); }
__device__ __forceinline__ uint32_t smem_u32(const void* p) {
    return (uint32_t)__cvta_generic_to_shared(p);
}
#define CP16(dst_u32, src_ptr) \
    asm volatile("cp.async.ca.shared.global [%0], [%1], 16;" :: "r"(dst_u32), "l"(src_ptr))
#define CP_COMMIT() asm volatile("cp.async.commit_group;")
#define CP_WAIT1()  asm volatile("cp.async.wait_group 1;")
#define CP_WAIT0()  asm volatile("cp.async.wait_group 0;")

__device__ __forceinline__ void mma8(float* c,
                                     uint32_t a0, uint32_t a1, uint32_t a2, uint32_t a3,
                                     uint32_t b0, uint32_t b1) {
    asm volatile(
        "mma.sync.aligned.m16n8k8.row.col.f32.tf32.tf32.f32 "
        "{%0,%1,%2,%3}, {%4,%5,%6,%7}, {%8,%9}, {%0,%1,%2,%3};"
        : "+f"(c[0]), "+f"(c[1]), "+f"(c[2]), "+f"(c[3])
        : "r"(a0), "r"(a1), "r"(a2), "r"(a3), "r"(b0), "r"(b1));
}

// ---------------------------------------------------------------------------
// tf32 rounding prepass
// ---------------------------------------------------------------------------
__global__ void round_tf32_kernel(const float* __restrict__ in,
                                  float* __restrict__ out, int n4)
{
    int i = blockIdx.x * blockDim.x + threadIdx.x;
    if (i < n4) {
        float4 v = reinterpret_cast<const float4*>(in)[i];
        reinterpret_cast<float4*>(out)[i] =
            make_float4(tf32f(v.x), tf32f(v.y), tf32f(v.z), tf32f(v.w));
    }
}

// ---------------------------------------------------------------------------
// TF32 GEMM: 128x128x32 CTA tile, 4 warps (2x2), 64x64 warp tile,
// cp.async 3-stage pipeline, ONE barrier per mainloop iteration.
// ---------------------------------------------------------------------------
#define GA 36
#define GB 132
#define STAGE_F (128*GA + 32*GB)               // floats per stage = 8832
#define GEMM_SMEM (3 * STAGE_F * 4)            // 105984 B

__global__ __launch_bounds__(128) void gemm_tf32(
    const float* __restrict__ A, const float* __restrict__ B,
    const float* __restrict__ bias, float* __restrict__ C,
    int M, int N, int K, int round_out)
{
    extern __shared__ float sm[];

    const int tid  = threadIdx.x;
    const int warp = tid >> 5, lane = tid & 31;
    const int wm = warp >> 1, wn = warp & 1;   // 2 x 2 warp grid
    const int g2 = lane >> 2, t4 = lane & 3;
    const int cRow = blockIdx.y, cCol = blockIdx.x;

    const float* Ab = A + (size_t)cRow * 128 * K;
    const float* Bb = B + cCol * 128;

    float c[4][8][4];
    #pragma unroll
    for (int mf = 0; mf < 4; mf++)
        #pragma unroll
        for (int nf = 0; nf < 8; nf++)
            #pragma unroll
            for (int i = 0; i < 4; i++) c[mf][nf][i] = 0.f;

    const int nk = K >> 5;

    // prologue: prefetch stages 0 and 1 (one commit group each)
    #pragma unroll
    for (int st = 0; st < 2; st++) {
        float* Ad = sm + st * STAGE_F;
        float* Bd = Ad + 128 * GA;
        const int k0 = st << 5;
        #pragma unroll
        for (int i = 0; i < 8; i++) {
            int idx = tid + i * 128;
            int r = idx >> 3, c4 = (idx & 7) << 2;
            CP16(smem_u32(Ad + r * GA + c4), Ab + (size_t)r * K + k0 + c4);
        }
        #pragma unroll
        for (int i = 0; i < 8; i++) {
            int idx = tid + i * 128;
            int r = idx >> 5, c4 = (idx & 31) << 2;
            CP16(smem_u32(Bd + r * GB + c4), Bb + (size_t)(k0 + r) * N + c4);
        }
        CP_COMMIT();
    }

    int stage = 0, pstage = 2;   // compute stage, prefetch stage
    for (int it = 0; it < nk; it++) {
        CP_WAIT1();              // stage `it` complete (2 groups in flight max)
        __syncthreads();         // all warps done with stage pstage's old data

        // prefetch it+2 into pstage (dead since iter it-1)
        if (it + 2 < nk) {
            const int k0 = (it + 2) << 5;
            float* Ad = sm + pstage * STAGE_F;
            float* Bd = Ad + 128 * GA;
            #pragma unroll
            for (int i = 0; i < 8; i++) {
                int idx = tid + i * 128;
                int r = idx >> 3, c4 = (idx & 7) << 2;
                CP16(smem_u32(Ad + r * GA + c4), Ab + (size_t)r * K + k0 + c4);
            }
            #pragma unroll
            for (int i = 0; i < 8; i++) {
                int idx = tid + i * 128;
                int r = idx >> 5, c4 = (idx & 31) << 2;
                CP16(smem_u32(Bd + r * GB + c4), Bb + (size_t)(k0 + r) * N + c4);
            }
        }
        CP_COMMIT();             // always commit (possibly empty) to keep counts

        const float* Ac = sm + stage * STAGE_F;
        const float* Bc = Ac + 128 * GA;

        #pragma unroll
        for (int ks = 0; ks < 4; ks++) {
            const int k = ks * 8;
            uint32_t a[4][4], b[8][2];
            #pragma unroll
            for (int mf = 0; mf < 4; mf++) {
                int r0 = wm * 64 + mf * 16 + g2;
                a[mf][0] = fbits(Ac[r0 * GA + k + t4]);
                a[mf][1] = fbits(Ac[(r0 + 8) * GA + k + t4]);
                a[mf][2] = fbits(Ac[r0 * GA + k + 4 + t4]);
                a[mf][3] = fbits(Ac[(r0 + 8) * GA + k + 4 + t4]);
            }
            #pragma unroll
            for (int nf = 0; nf < 8; nf++) {
                int cc = wn * 64 + nf * 8 + g2;
                b[nf][0] = fbits(Bc[(k + t4) * GB + cc]);
                b[nf][1] = fbits(Bc[(k + 4 + t4) * GB + cc]);
            }
            #pragma unroll
            for (int mf = 0; mf < 4; mf++)
                #pragma unroll
                for (int nf = 0; nf < 8; nf++)
                    mma8(c[mf][nf], a[mf][0], a[mf][1], a[mf][2], a[mf][3],
                         b[nf][0], b[nf][1]);
        }
        stage = (stage + 1) % 3;
        pstage = (pstage + 1) % 3;
    }

    #pragma unroll
    for (int nf = 0; nf < 8; nf++) {
        int cc = cCol * 128 + wn * 64 + nf * 8 + t4 * 2;
        float b0 = bias[cc], b1 = bias[cc + 1];
        #pragma unroll
        for (int mf = 0; mf < 4; mf++) {
            int r0 = cRow * 128 + wm * 64 + mf * 16 + g2;
            float v00 = c[mf][nf][0] + b0, v01 = c[mf][nf][1] + b1;
            float v10 = c[mf][nf][2] + b0, v11 = c[mf][nf][3] + b1;
            if (round_out) {
                v00 = tf32f(v00); v01 = tf32f(v01);
                v10 = tf32f(v10); v11 = tf32f(v11);
            }
            *reinterpret_cast<float2*>(C + (size_t)r0 * N + cc)       = make_float2(v00, v01);
            *reinterpret_cast<float2*>(C + (size_t)(r0 + 8) * N + cc) = make_float2(v10, v11);
        }
    }
}

// ---------------------------------------------------------------------------
// TF32 causal flash attention: BQ=128, BKV=64, 256 threads (8 warps).
// Each warp owns 16 full query rows -> softmax is warp-local (quad shuffles),
// P rows are warp-private: ONE __syncthreads per KV tile (for K/V only).
// ---------------------------------------------------------------------------
#define BQ  128
#define BKV 64
#define QS_S 68
#define KS_S 68
#define VS_S 72
#define PS_S 68
#define SCALE_L2E 0.18033688011112042f   // 0.125 * log2(e)
#define FLASH_SMEM ((128*QS_S + 2*64*KS_S + 2*64*VS_S + 128*PS_S) * 4)  // 141312 B

__global__ __launch_bounds__(256, 1) void flash_tf32(
    const float* __restrict__ qkv, float* __restrict__ attn_out)
{
    extern __shared__ float sm[];
    float* Qs = sm;                       // [128][68]
    float* Ks = Qs + 128 * QS_S;          // [2][64][68]
    float* Vs = Ks + 2 * 64 * KS_S;       // [2][64][72]
    float* Ps = Vs + 2 * 64 * VS_S;       // [128][68]

    const int qb = gridDim.x - 1 - blockIdx.x;   // heavy blocks first
    const int h = blockIdx.y, b = blockIdx.z;
    const int tid = threadIdx.x, warp = tid >> 5, lane = tid & 31;
    const int g2 = lane >> 2, t4 = lane & 3;
    const int q0 = qb * BQ;
    const int kr = tid >> 4, kc = (tid & 15) << 2;

    // Q tile: 128x64, scaled by 0.125*log2e, tf32-rounded
    #pragma unroll
    for (int i = 0; i < 8; i++) {
        int idx = tid + i * 256;
        int r = idx >> 4, c4 = (idx & 15) << 2;
        float4 v = *reinterpret_cast<const float4*>(
            qkv + (size_t)(b * SEQ + q0 + r) * 3072 + h * 64 + c4);
        Qs[r * QS_S + c4 + 0] = tf32f(v.x * SCALE_L2E);
        Qs[r * QS_S + c4 + 1] = tf32f(v.y * SCALE_L2E);
        Qs[r * QS_S + c4 + 2] = tf32f(v.z * SCALE_L2E);
        Qs[r * QS_S + c4 + 3] = tf32f(v.w * SCALE_L2E);
    }

    const int r0l = warp * 16 + g2;        // this thread's rows: r0l, r0l+8
    const int grow0 = q0 + r0l, grow1 = grow0 + 8;
    float m0 = -1e30f, m1 = -1e30f, l0 = 0.f, l1 = 0.f;
    float o[8][4];
    #pragma unroll
    for (int nf = 0; nf < 8; nf++)
        #pragma unroll
        for (int i = 0; i < 4; i++) o[nf][i] = 0.f;

    const int nkv = 2 * qb + 2;            // 64-wide tiles covering [0, q0+127]

    // prefetch KV tile 0 (stage 0)
    #pragma unroll
    for (int i = 0; i < 4; i++) {
        int r = kr + i * 16;
        size_t base = (size_t)(b * SEQ + r) * 3072 + h * 64 + kc;
        CP16(smem_u32(Ks + r * KS_S + kc), qkv + base + 1024);
        CP16(smem_u32(Vs + r * VS_S + kc), qkv + base + 2048);
    }
    CP_COMMIT();

    for (int t = 0; t < nkv; t++) {
        CP_WAIT0();
        __syncthreads();     // K/V tile t visible; all warps done with other stage

        if (t + 1 < nkv) {
            const int kv1 = (t + 1) * BKV;
            float* Kd = Ks + ((t + 1) & 1) * 64 * KS_S;
            float* Vd = Vs + ((t + 1) & 1) * 64 * VS_S;
            #pragma unroll
            for (int i = 0; i < 4; i++) {
                int r = kr + i * 16;
                size_t base = (size_t)(b * SEQ + kv1 + r) * 3072 + h * 64 + kc;
                CP16(smem_u32(Kd + r * KS_S + kc), qkv + base + 1024);
                CP16(smem_u32(Vd + r * VS_S + kc), qkv + base + 2048);
            }
            CP_COMMIT();
        }

        const float* Kc = Ks + (t & 1) * 64 * KS_S;
        const float* Vc = Vs + (t & 1) * 64 * VS_S;

        // ---- S = Qs(rows warp*16..+16) @ K^T (all 64 cols) ----
        float s[8][4];
        #pragma unroll
        for (int nf = 0; nf < 8; nf++)
            #pragma unroll
            for (int i = 0; i < 4; i++) s[nf][i] = 0.f;

        #pragma unroll
        for (int ks = 0; ks < 8; ks++) {
            const int k = ks * 8;
            uint32_t a0 = fbits(Qs[r0l * QS_S + k + t4]);
            uint32_t a1 = fbits(Qs[(r0l + 8) * QS_S + k + t4]);
            uint32_t a2 = fbits(Qs[r0l * QS_S + k + 4 + t4]);
            uint32_t a3 = fbits(Qs[(r0l + 8) * QS_S + k + 4 + t4]);
            #pragma unroll
            for (int nf = 0; nf < 8; nf++) {
                int cc = nf * 8 + g2;
                uint32_t b0 = fbits(Kc[cc * KS_S + k + t4]);
                uint32_t b1 = fbits(Kc[cc * KS_S + k + 4 + t4]);
                mma8(s[nf], a0, a1, a2, a3, b0, b1);
            }
        }

        // ---- mask + warp-local (quad) row max ----
        const bool nm = (t >= nkv - 2);
        float mx0 = -1e30f, mx1 = -1e30f;
        #pragma unroll
        for (int nf = 0; nf < 8; nf++) {
            #pragma unroll
            for (int j = 0; j < 2; j++) {
                int gc = t * BKV + nf * 8 + t4 * 2 + j;
                if (nm && gc > grow0) s[nf][j]     = -1e30f;
                if (nm && gc > grow1) s[nf][2 + j] = -1e30f;
                mx0 = fmaxf(mx0, s[nf][j]);
                mx1 = fmaxf(mx1, s[nf][2 + j]);
            }
        }
        mx0 = fmaxf(mx0, __shfl_xor_sync(0xffffffffu, mx0, 1));
        mx0 = fmaxf(mx0, __shfl_xor_sync(0xffffffffu, mx0, 2));
        mx1 = fmaxf(mx1, __shfl_xor_sync(0xffffffffu, mx1, 1));
        mx1 = fmaxf(mx1, __shfl_xor_sync(0xffffffffu, mx1, 2));

        const float mn0 = fmaxf(m0, mx0);
        const float mn1 = fmaxf(m1, mx1);
        const float a0s = ex2(m0 - mn0);
        const float a1s = ex2(m1 - mn1);

        float ps0 = 0.f, ps1 = 0.f;
        #pragma unroll
        for (int nf = 0; nf < 8; nf++) {
            float p00 = ex2(s[nf][0] - mn0);
            float p01 = ex2(s[nf][1] - mn0);
            float p10 = ex2(s[nf][2] - mn1);
            float p11 = ex2(s[nf][3] - mn1);
            ps0 += p00 + p01; ps1 += p10 + p11;
            int cc = nf * 8 + t4 * 2;
            *reinterpret_cast<float2*>(&Ps[r0l * PS_S + cc]) =
                make_float2(tf32f(p00), tf32f(p01));
            *reinterpret_cast<float2*>(&Ps[(r0l + 8) * PS_S + cc]) =
                make_float2(tf32f(p10), tf32f(p11));
        }
        ps0 += __shfl_xor_sync(0xffffffffu, ps0, 1);
        ps0 += __shfl_xor_sync(0xffffffffu, ps0, 2);
        ps1 += __shfl_xor_sync(0xffffffffu, ps1, 1);
        ps1 += __shfl_xor_sync(0xffffffffu, ps1, 2);
        l0 = l0 * a0s + ps0;
        l1 = l1 * a1s + ps1;
        m0 = mn0; m1 = mn1;

        // rescale O
        #pragma unroll
        for (int nf = 0; nf < 8; nf++) {
            o[nf][0] *= a0s; o[nf][1] *= a0s;
            o[nf][2] *= a1s; o[nf][3] *= a1s;
        }
        __syncwarp();   // P rows written by this warp's lanes, read cross-lane

        // ---- O += P @ V (own rows, all 64 dims) ----
        #pragma unroll
        for (int ks = 0; ks < 8; ks++) {
            const int k = ks * 8;
            uint32_t a0 = fbits(Ps[r0l * PS_S + k + t4]);
            uint32_t a1 = fbits(Ps[(r0l + 8) * PS_S + k + t4]);
            uint32_t a2 = fbits(Ps[r0l * PS_S + k + 4 + t4]);
            uint32_t a3 = fbits(Ps[(r0l + 8) * PS_S + k + 4 + t4]);
            #pragma unroll
            for (int nf = 0; nf < 8; nf++) {
                int cc = nf * 8 + g2;
                uint32_t b0 = fbits(Vc[(k + t4) * VS_S + cc]);
                uint32_t b1 = fbits(Vc[(k + 4 + t4) * VS_S + cc]);
                mma8(o[nf], a0, a1, a2, a3, b0, b1);
            }
        }
    }

    const float inv0 = 1.f / l0, inv1 = 1.f / l1;
    #pragma unroll
    for (int nf = 0; nf < 8; nf++) {
        int cc = nf * 8 + t4 * 2;
        float* p0 = attn_out + (size_t)(b * SEQ + grow0) * HID + h * 64 + cc;
        float* p1 = attn_out + (size_t)(b * SEQ + grow1) * HID + h * 64 + cc;
        *reinterpret_cast<float2*>(p0) =
            make_float2(tf32f(o[nf][0] * inv0), tf32f(o[nf][1] * inv0));
        *reinterpret_cast<float2*>(p1) =
            make_float2(tf32f(o[nf][2] * inv1), tf32f(o[nf][3] * inv1));
    }
}

// ---------------------------------------------------------------------------
extern "C" void kernel_launch(void* const* d_in, const int* in_sizes, int n_in,
                              void* d_out, int out_size)
{
    const float* x     = (const float*)d_in[0];
    const float* w_qkv = (const float*)d_in[1];
    const float* b_qkv = (const float*)d_in[2];
    const float* w_out = (const float*)d_in[3];
    const float* b_out = (const float*)d_in[4];
    float* out = (float*)d_out;

    float *qkv, *attn, *xc, *w1, *w2;
    cudaGetSymbolAddress((void**)&qkv,  g_qkv);
    cudaGetSymbolAddress((void**)&attn, g_attn);
    cudaGetSymbolAddress((void**)&xc,   g_xc);
    cudaGetSymbolAddress((void**)&w1,   g_w1);
    cudaGetSymbolAddress((void**)&w2,   g_w2);

    cudaFuncSetAttribute(gemm_tf32,  cudaFuncAttributeMaxDynamicSharedMemorySize, GEMM_SMEM);
    cudaFuncSetAttribute(flash_tf32, cudaFuncAttributeMaxDynamicSharedMemorySize, FLASH_SMEM);

    // 0) round inputs to tf32
    round_tf32_kernel<<<(NTOK * HID / 4 + 255) / 256, 256>>>(x, xc, NTOK * HID / 4);
    round_tf32_kernel<<<(HID * 3 * HID / 4 + 255) / 256, 256>>>(w_qkv, w1, HID * 3 * HID / 4);
    round_tf32_kernel<<<(HID * HID / 4 + 255) / 256, 256>>>(w_out, w2, HID * HID / 4);

    // 1) qkv = xc @ w1 + b_qkv (output rounded to tf32)
    dim3 g1(3 * HID / 128, NTOK / 128);
    gemm_tf32<<<g1, 128, GEMM_SMEM>>>(xc, w1, b_qkv, qkv, NTOK, 3 * HID, HID, 1);

    // 2) causal flash attention
    dim3 g2(SEQ / BQ, NHEAD, BATCH);
    flash_tf32<<<g2, 256, FLASH_SMEM>>>(qkv, attn);

    // 3) out = attn @ w2 + b_out
    dim3 g3(HID / 128, NTOK / 128);
    gemm_tf32<<<g3, 128, GEMM_SMEM>>>(attn, w2, b_out, out, NTOK, HID, HID, 0);
}

// round 9
// speedup vs baseline: 1.0452x; 1.0452x over previous
#include <cuda_runtime.h>
#include <cstdint>

#define BATCH 2
#define SEQ   2048
#define HID   1024
#define NHEAD 16
#define HDIM  64
#define NTOK  (BATCH*SEQ)

// Scratch (device globals: allocation-free rule)
__device__ float g_qkv[NTOK * 3 * HID];   // (B,S,3,NH,HD) tf32-rounded
__device__ float g_attn[NTOK * HID];      // tf32-rounded
__device__ float g_xc[NTOK * HID];
__device__ float g_w1[HID * 3 * HID];
__device__ float g_w2[HID * HID];

// ---------------------------------------------------------------------------
__device__ __forceinline__ float tf32f(float x) {
    uint32_t u;
    asm("cvt.rna.tf32.f32 %0, %1;" : "=r"(u) : "f"(x));
    return __uint_as_float(u);
}
__device__ __forceinline__ float ex2(float x) {
    float y;
    asm("ex2.approx.ftz.f32 %0, %1;" : "=f"(y) : "f"(x));
    return y;
}
__device__ __forceinline__ uint32_t fbits(float x) { return __float_as_uint(x); }
__device__ __forceinline__ uint32_t smem_u32(const void* p) {
    return (uint32_t)__cvta_generic_to_shared(p);
}
#define CP16(dst_u32, src_ptr) \
    asm volatile("cp.async.ca.shared.global [%0], [%1], 16;" :: "r"(dst_u32), "l"(src_ptr))
#define CP_COMMIT() asm volatile("cp.async.commit_group;")
#define CP_WAIT0()  asm volatile("cp.async.wait_group 0;")

__device__ __forceinline__ void mma8(float* c,
                                     uint32_t a0, uint32_t a1, uint32_t a2, uint32_t a3,
                                     uint32_t b0, uint32_t b1) {
    asm volatile(
        "mma.sync.aligned.m16n8k8.row.col.f32.tf32.tf32.f32 "
        "{%0,%1,%2,%3}, {%4,%5,%6,%7}, {%8,%9}, {%0,%1,%2,%3};"
        : "+f"(c[0]), "+f"(c[1]), "+f"(c[2]), "+f"(c[3])
        : "r"(a0), "r"(a1), "r"(a2), "r"(a3), "r"(b0), "r"(b1));
}

// ---------------------------------------------------------------------------
// tf32 rounding prepass
// ---------------------------------------------------------------------------
__global__ void round_tf32_kernel(const float* __restrict__ in,
                                  float* __restrict__ out, int n4)
{
    int i = blockIdx.x * blockDim.x + threadIdx.x;
    if (i < n4) {
        float4 v = reinterpret_cast<const float4*>(in)[i];
        reinterpret_cast<float4*>(out)[i] =
            make_float4(tf32f(v.x), tf32f(v.y), tf32f(v.z), tf32f(v.w));
    }
}

// ---------------------------------------------------------------------------
// TF32 GEMM: 128x128 CTA tile, BK=64, 256 threads (8 warps, 2x4 grid,
// 64x32 warp tiles). 2-stage cp.async, ONE barrier per 8 ks-steps:
//   wait stage t -> barrier -> prefetch t+1 into other stage -> compute t.
// ---------------------------------------------------------------------------
#define GA 68
#define GB 132
#define STAGE_F (128*GA + 64*GB)               // 17152 floats
#define GEMM_SMEM (2 * STAGE_F * 4)            // 137216 B

__global__ __launch_bounds__(256, 1) void gemm_tf32(
    const float* __restrict__ A, const float* __restrict__ B,
    const float* __restrict__ bias, float* __restrict__ C,
    int M, int N, int K, int round_out)
{
    extern __shared__ float sm[];

    const int tid  = threadIdx.x;
    const int warp = tid >> 5, lane = tid & 31;
    const int wm = warp >> 2, wn = warp & 3;   // 2 x 4 warp grid
    const int g2 = lane >> 2, t4 = lane & 3;
    const int cRow = blockIdx.y, cCol = blockIdx.x;

    const float* Ab = A + (size_t)cRow * 128 * K;
    const float* Bb = B + cCol * 128;

    float c[4][4][4];
    #pragma unroll
    for (int mf = 0; mf < 4; mf++)
        #pragma unroll
        for (int nf = 0; nf < 4; nf++)
            #pragma unroll
            for (int i = 0; i < 4; i++) c[mf][nf][i] = 0.f;

    const int nk = K >> 6;    // BK=64

    // prologue: prefetch stage 0
    {
        float* Ad = sm;
        float* Bd = sm + 128 * GA;
        #pragma unroll
        for (int i = 0; i < 8; i++) {                 // A: 128x64 = 2048 float4
            int idx = tid + i * 256;
            int r = idx >> 4, c4 = (idx & 15) << 2;
            CP16(smem_u32(Ad + r * GA + c4), Ab + (size_t)r * K + c4);
        }
        #pragma unroll
        for (int i = 0; i < 8; i++) {                 // B: 64x128 = 2048 float4
            int idx = tid + i * 256;
            int r = idx >> 5, c4 = (idx & 31) << 2;
            CP16(smem_u32(Bd + r * GB + c4), Bb + (size_t)r * N + c4);
        }
        CP_COMMIT();
    }

    for (int it = 0; it < nk; it++) {
        CP_WAIT0();              // stage `it` is the only group in flight
        __syncthreads();         // + proves all warps done with the other stage

        if (it + 1 < nk) {       // prefetch it+1 into the other stage
            const int k0 = (it + 1) << 6;
            float* Ad = sm + ((it + 1) & 1) * STAGE_F;
            float* Bd = Ad + 128 * GA;
            #pragma unroll
            for (int i = 0; i < 8; i++) {
                int idx = tid + i * 256;
                int r = idx >> 4, c4 = (idx & 15) << 2;
                CP16(smem_u32(Ad + r * GA + c4), Ab + (size_t)r * K + k0 + c4);
            }
            #pragma unroll
            for (int i = 0; i < 8; i++) {
                int idx = tid + i * 256;
                int r = idx >> 5, c4 = (idx & 31) << 2;
                CP16(smem_u32(Bd + r * GB + c4), Bb + (size_t)(k0 + r) * N + c4);
            }
            CP_COMMIT();
        }

        const float* Ac = sm + (it & 1) * STAGE_F;
        const float* Bc = Ac + 128 * GA;

        #pragma unroll
        for (int ks = 0; ks < 8; ks++) {
            const int k = ks * 8;
            uint32_t a[4][4], b[4][2];
            #pragma unroll
            for (int mf = 0; mf < 4; mf++) {
                int r0 = wm * 64 + mf * 16 + g2;
                a[mf][0] = fbits(Ac[r0 * GA + k + t4]);
                a[mf][1] = fbits(Ac[(r0 + 8) * GA + k + t4]);
                a[mf][2] = fbits(Ac[r0 * GA + k + 4 + t4]);
                a[mf][3] = fbits(Ac[(r0 + 8) * GA + k + 4 + t4]);
            }
            #pragma unroll
            for (int nf = 0; nf < 4; nf++) {
                int cc = wn * 32 + nf * 8 + g2;
                b[nf][0] = fbits(Bc[(k + t4) * GB + cc]);
                b[nf][1] = fbits(Bc[(k + 4 + t4) * GB + cc]);
            }
            #pragma unroll
            for (int mf = 0; mf < 4; mf++)
                #pragma unroll
                for (int nf = 0; nf < 4; nf++)
                    mma8(c[mf][nf], a[mf][0], a[mf][1], a[mf][2], a[mf][3],
                         b[nf][0], b[nf][1]);
        }
    }

    #pragma unroll
    for (int nf = 0; nf < 4; nf++) {
        int cc = cCol * 128 + wn * 32 + nf * 8 + t4 * 2;
        float b0 = bias[cc], b1 = bias[cc + 1];
        #pragma unroll
        for (int mf = 0; mf < 4; mf++) {
            int r0 = cRow * 128 + wm * 64 + mf * 16 + g2;
            float v00 = c[mf][nf][0] + b0, v01 = c[mf][nf][1] + b1;
            float v10 = c[mf][nf][2] + b0, v11 = c[mf][nf][3] + b1;
            if (round_out) {
                v00 = tf32f(v00); v01 = tf32f(v01);
                v10 = tf32f(v10); v11 = tf32f(v11);
            }
            *reinterpret_cast<float2*>(C + (size_t)r0 * N + cc)       = make_float2(v00, v01);
            *reinterpret_cast<float2*>(C + (size_t)(r0 + 8) * N + cc) = make_float2(v10, v11);
        }
    }
}

// ---------------------------------------------------------------------------
// TF32 causal flash attention: BQ=128, BKV=64, 256 threads (8 warps).
// Unchanged from R8 (measured ~67% tensor).
// ---------------------------------------------------------------------------
#define BQ  128
#define BKV 64
#define QS_S 68
#define KS_S 68
#define VS_S 72
#define PS_S 68
#define SCALE_L2E 0.18033688011112042f   // 0.125 * log2(e)
#define FLASH_SMEM ((128*QS_S + 2*64*KS_S + 2*64*VS_S + 128*PS_S) * 4)  // 141312 B

__global__ __launch_bounds__(256, 1) void flash_tf32(
    const float* __restrict__ qkv, float* __restrict__ attn_out)
{
    extern __shared__ float sm[];
    float* Qs = sm;                       // [128][68]
    float* Ks = Qs + 128 * QS_S;          // [2][64][68]
    float* Vs = Ks + 2 * 64 * KS_S;       // [2][64][72]
    float* Ps = Vs + 2 * 64 * VS_S;       // [128][68]

    const int qb = gridDim.x - 1 - blockIdx.x;   // heavy blocks first
    const int h = blockIdx.y, b = blockIdx.z;
    const int tid = threadIdx.x, warp = tid >> 5, lane = tid & 31;
    const int g2 = lane >> 2, t4 = lane & 3;
    const int q0 = qb * BQ;
    const int kr = tid >> 4, kc = (tid & 15) << 2;

    #pragma unroll
    for (int i = 0; i < 8; i++) {
        int idx = tid + i * 256;
        int r = idx >> 4, c4 = (idx & 15) << 2;
        float4 v = *reinterpret_cast<const float4*>(
            qkv + (size_t)(b * SEQ + q0 + r) * 3072 + h * 64 + c4);
        Qs[r * QS_S + c4 + 0] = tf32f(v.x * SCALE_L2E);
        Qs[r * QS_S + c4 + 1] = tf32f(v.y * SCALE_L2E);
        Qs[r * QS_S + c4 + 2] = tf32f(v.z * SCALE_L2E);
        Qs[r * QS_S + c4 + 3] = tf32f(v.w * SCALE_L2E);
    }

    const int r0l = warp * 16 + g2;
    const int grow0 = q0 + r0l, grow1 = grow0 + 8;
    float m0 = -1e30f, m1 = -1e30f, l0 = 0.f, l1 = 0.f;
    float o[8][4];
    #pragma unroll
    for (int nf = 0; nf < 8; nf++)
        #pragma unroll
        for (int i = 0; i < 4; i++) o[nf][i] = 0.f;

    const int nkv = 2 * qb + 2;

    #pragma unroll
    for (int i = 0; i < 4; i++) {
        int r = kr + i * 16;
        size_t base = (size_t)(b * SEQ + r) * 3072 + h * 64 + kc;
        CP16(smem_u32(Ks + r * KS_S + kc), qkv + base + 1024);
        CP16(smem_u32(Vs + r * VS_S + kc), qkv + base + 2048);
    }
    CP_COMMIT();

    for (int t = 0; t < nkv; t++) {
        CP_WAIT0();
        __syncthreads();

        if (t + 1 < nkv) {
            const int kv1 = (t + 1) * BKV;
            float* Kd = Ks + ((t + 1) & 1) * 64 * KS_S;
            float* Vd = Vs + ((t + 1) & 1) * 64 * VS_S;
            #pragma unroll
            for (int i = 0; i < 4; i++) {
                int r = kr + i * 16;
                size_t base = (size_t)(b * SEQ + kv1 + r) * 3072 + h * 64 + kc;
                CP16(smem_u32(Kd + r * KS_S + kc), qkv + base + 1024);
                CP16(smem_u32(Vd + r * VS_S + kc), qkv + base + 2048);
            }
            CP_COMMIT();
        }

        const float* Kc = Ks + (t & 1) * 64 * KS_S;
        const float* Vc = Vs + (t & 1) * 64 * VS_S;

        float s[8][4];
        #pragma unroll
        for (int nf = 0; nf < 8; nf++)
            #pragma unroll
            for (int i = 0; i < 4; i++) s[nf][i] = 0.f;

        #pragma unroll
        for (int ks = 0; ks < 8; ks++) {
            const int k = ks * 8;
            uint32_t a0 = fbits(Qs[r0l * QS_S + k + t4]);
            uint32_t a1 = fbits(Qs[(r0l + 8) * QS_S + k + t4]);
            uint32_t a2 = fbits(Qs[r0l * QS_S + k + 4 + t4]);
            uint32_t a3 = fbits(Qs[(r0l + 8) * QS_S + k + 4 + t4]);
            #pragma unroll
            for (int nf = 0; nf < 8; nf++) {
                int cc = nf * 8 + g2;
                uint32_t b0 = fbits(Kc[cc * KS_S + k + t4]);
                uint32_t b1 = fbits(Kc[cc * KS_S + k + 4 + t4]);
                mma8(s[nf], a0, a1, a2, a3, b0, b1);
            }
        }

        const bool nm = (t >= nkv - 2);
        float mx0 = -1e30f, mx1 = -1e30f;
        #pragma unroll
        for (int nf = 0; nf < 8; nf++) {
            #pragma unroll
            for (int j = 0; j < 2; j++) {
                int gc = t * BKV + nf * 8 + t4 * 2 + j;
                if (nm && gc > grow0) s[nf][j]     = -1e30f;
                if (nm && gc > grow1) s[nf][2 + j] = -1e30f;
                mx0 = fmaxf(mx0, s[nf][j]);
                mx1 = fmaxf(mx1, s[nf][2 + j]);
            }
        }
        mx0 = fmaxf(mx0, __shfl_xor_sync(0xffffffffu, mx0, 1));
        mx0 = fmaxf(mx0, __shfl_xor_sync(0xffffffffu, mx0, 2));
        mx1 = fmaxf(mx1, __shfl_xor_sync(0xffffffffu, mx1, 1));
        mx1 = fmaxf(mx1, __shfl_xor_sync(0xffffffffu, mx1, 2));

        const float mn0 = fmaxf(m0, mx0);
        const float mn1 = fmaxf(m1, mx1);
        const float a0s = ex2(m0 - mn0);
        const float a1s = ex2(m1 - mn1);

        float ps0 = 0.f, ps1 = 0.f;
        #pragma unroll
        for (int nf = 0; nf < 8; nf++) {
            float p00 = ex2(s[nf][0] - mn0);
            float p01 = ex2(s[nf][1] - mn0);
            float p10 = ex2(s[nf][2] - mn1);
            float p11 = ex2(s[nf][3] - mn1);
            ps0 += p00 + p01; ps1 += p10 + p11;
            int cc = nf * 8 + t4 * 2;
            *reinterpret_cast<float2*>(&Ps[r0l * PS_S + cc]) =
                make_float2(tf32f(p00), tf32f(p01));
            *reinterpret_cast<float2*>(&Ps[(r0l + 8) * PS_S + cc]) =
                make_float2(tf32f(p10), tf32f(p11));
        }
        ps0 += __shfl_xor_sync(0xffffffffu, ps0, 1);
        ps0 += __shfl_xor_sync(0xffffffffu, ps0, 2);
        ps1 += __shfl_xor_sync(0xffffffffu, ps1, 1);
        ps1 += __shfl_xor_sync(0xffffffffu, ps1, 2);
        l0 = l0 * a0s + ps0;
        l1 = l1 * a1s + ps1;
        m0 = mn0; m1 = mn1;

        #pragma unroll
        for (int nf = 0; nf < 8; nf++) {
            o[nf][0] *= a0s; o[nf][1] *= a0s;
            o[nf][2] *= a1s; o[nf][3] *= a1s;
        }
        __syncwarp();

        #pragma unroll
        for (int ks = 0; ks < 8; ks++) {
            const int k = ks * 8;
            uint32_t a0 = fbits(Ps[r0l * PS_S + k + t4]);
            uint32_t a1 = fbits(Ps[(r0l + 8) * PS_S + k + t4]);
            uint32_t a2 = fbits(Ps[r0l * PS_S + k + 4 + t4]);
            uint32_t a3 = fbits(Ps[(r0l + 8) * PS_S + k + 4 + t4]);
            #pragma unroll
            for (int nf = 0; nf < 8; nf++) {
                int cc = nf * 8 + g2;
                uint32_t b0 = fbits(Vc[(k + t4) * VS_S + cc]);
                uint32_t b1 = fbits(Vc[(k + 4 + t4) * VS_S + cc]);
                mma8(o[nf], a0, a1, a2, a3, b0, b1);
            }
        }
    }

    const float inv0 = 1.f / l0, inv1 = 1.f / l1;
    #pragma unroll
    for (int nf = 0; nf < 8; nf++) {
        int cc = nf * 8 + t4 * 2;
        float* p0 = attn_out + (size_t)(b * SEQ + grow0) * HID + h * 64 + cc;
        float* p1 = attn_out + (size_t)(b * SEQ + grow1) * HID + h * 64 + cc;
        *reinterpret_cast<float2*>(p0) =
            make_float2(tf32f(o[nf][0] * inv0), tf32f(o[nf][1] * inv0));
        *reinterpret_cast<float2*>(p1) =
            make_float2(tf32f(o[nf][2] * inv1), tf32f(o[nf][3] * inv1));
    }
}

// ---------------------------------------------------------------------------
extern "C" void kernel_launch(void* const* d_in, const int* in_sizes, int n_in,
                              void* d_out, int out_size)
{
    const float* x     = (const float*)d_in[0];
    const float* w_qkv = (const float*)d_in[1];
    const float* b_qkv = (const float*)d_in[2];
    const float* w_out = (const float*)d_in[3];
    const float* b_out = (const float*)d_in[4];
    float* out = (float*)d_out;

    float *qkv, *attn, *xc, *w1, *w2;
    cudaGetSymbolAddress((void**)&qkv,  g_qkv);
    cudaGetSymbolAddress((void**)&attn, g_attn);
    cudaGetSymbolAddress((void**)&xc,   g_xc);
    cudaGetSymbolAddress((void**)&w1,   g_w1);
    cudaGetSymbolAddress((void**)&w2,   g_w2);

    cudaFuncSetAttribute(gemm_tf32,  cudaFuncAttributeMaxDynamicSharedMemorySize, GEMM_SMEM);
    cudaFuncSetAttribute(flash_tf32, cudaFuncAttributeMaxDynamicSharedMemorySize, FLASH_SMEM);

    // 0) round inputs to tf32
    round_tf32_kernel<<<(NTOK * HID / 4 + 255) / 256, 256>>>(x, xc, NTOK * HID / 4);
    round_tf32_kernel<<<(HID * 3 * HID / 4 + 255) / 256, 256>>>(w_qkv, w1, HID * 3 * HID / 4);
    round_tf32_kernel<<<(HID * HID / 4 + 255) / 256, 256>>>(w_out, w2, HID * HID / 4);

    // 1) qkv = xc @ w1 + b_qkv (output rounded to tf32)
    dim3 g1(3 * HID / 128, NTOK / 128);
    gemm_tf32<<<g1, 256, GEMM_SMEM>>>(xc, w1, b_qkv, qkv, NTOK, 3 * HID, HID, 1);

    // 2) causal flash attention
    dim3 g2(SEQ / BQ, NHEAD, BATCH);
    flash_tf32<<<g2, 256, FLASH_SMEM>>>(qkv, attn);

    // 3) out = attn @ w2 + b_out
    dim3 g3(HID / 128, NTOK / 128);
    gemm_tf32<<<g3, 256, GEMM_SMEM>>>(attn, w2, b_out, out, NTOK, HID, HID, 0);
}

// round 10
// speedup vs baseline: 1.0760x; 1.0295x over previous
#include <cuda_runtime.h>
#include <cstdint>

#define BATCH 2
#define SEQ   2048
#define HID   1024
#define NHEAD 16
#define HDIM  64
#define NTOK  (BATCH*SEQ)

// Scratch (device globals: allocation-free rule)
__device__ float g_qkv[NTOK * 3 * HID];   // (B,S,3,NH,HD) tf32-rounded
__device__ float g_attn[NTOK * HID];      // tf32-rounded
__device__ float g_xc[NTOK * HID];
__device__ float g_w1[HID * 3 * HID];
__device__ float g_w2[HID * HID];

// ---------------------------------------------------------------------------
__device__ __forceinline__ float tf32f(float x) {
    uint32_t u;
    asm("cvt.rna.tf32.f32 %0, %1;" : "=r"(u) : "f"(x));
    return __uint_as_float(u);
}
__device__ __forceinline__ float ex2(float x) {
    float y;
    asm("ex2.approx.ftz.f32 %0, %1;" : "=f"(y) : "f"(x));
    return y;
}
__device__ __forceinline__ uint32_t fbits(float x) { return __float_as_uint(x); }
__device__ __forceinline__ uint32_t smem_u32(const void* p) {
    return (uint32_t)__cvta_generic_to_shared(p);
}
#define CP16(dst_u32, src_ptr) \
    asm volatile("cp.async.ca.shared.global [%0], [%1], 16;" :: "r"(dst_u32), "l"(src_ptr))
#define CP_COMMIT() asm volatile("cp.async.commit_group;")
#define CP_WAIT0()  asm volatile("cp.async.wait_group 0;")

__device__ __forceinline__ void mma8(float* c,
                                     uint32_t a0, uint32_t a1, uint32_t a2, uint32_t a3,
                                     uint32_t b0, uint32_t b1) {
    asm volatile(
        "mma.sync.aligned.m16n8k8.row.col.f32.tf32.tf32.f32 "
        "{%0,%1,%2,%3}, {%4,%5,%6,%7}, {%8,%9}, {%0,%1,%2,%3};"
        : "+f"(c[0]), "+f"(c[1]), "+f"(c[2]), "+f"(c[3])
        : "r"(a0), "r"(a1), "r"(a2), "r"(a3), "r"(b0), "r"(b1));
}

// ---------------------------------------------------------------------------
// Fused tf32 rounding prepass: x -> xc, w_qkv -> w1, w_out -> w2 in ONE launch.
// ---------------------------------------------------------------------------
#define N4_X  (NTOK * HID / 4)          // 1048576
#define N4_W1 (HID * 3 * HID / 4)       // 786432
#define N4_W2 (HID * HID / 4)           // 262144
#define N4_ALL (N4_X + N4_W1 + N4_W2)   // 2097152

__global__ void round3_kernel(const float* __restrict__ x,  float* __restrict__ xc,
                              const float* __restrict__ w1i, float* __restrict__ w1o,
                              const float* __restrict__ w2i, float* __restrict__ w2o)
{
    int i = blockIdx.x * blockDim.x + threadIdx.x;
    const float4* in;
    float4* out;
    int idx;
    if (i < N4_X)              { in = (const float4*)x;   out = (float4*)xc;  idx = i; }
    else if (i < N4_X + N4_W1) { in = (const float4*)w1i; out = (float4*)w1o; idx = i - N4_X; }
    else if (i < N4_ALL)       { in = (const float4*)w2i; out = (float4*)w2o; idx = i - N4_X - N4_W1; }
    else return;
    float4 v = in[idx];
    out[idx] = make_float4(tf32f(v.x), tf32f(v.y), tf32f(v.z), tf32f(v.w));
}

// ---------------------------------------------------------------------------
// TF32 GEMM: 128x128x32 CTA tile, 256 threads (8 warps, 2x4 grid, 64x32 warp
// tiles), 2-stage cp.async, 70KB smem -> 2 CTAs/SM, ONE barrier per iter:
//   wait stage t -> barrier -> prefetch t+1 into other stage -> compute t.
// ---------------------------------------------------------------------------
#define GA 36
#define GB 132
#define STAGE_F (128*GA + 32*GB)               // 8832 floats
#define GEMM_SMEM (2 * STAGE_F * 4)            // 70656 B

__global__ __launch_bounds__(256, 2) void gemm_tf32(
    const float* __restrict__ A, const float* __restrict__ B,
    const float* __restrict__ bias, float* __restrict__ C,
    int M, int N, int K, int round_out)
{
    extern __shared__ float sm[];

    const int tid  = threadIdx.x;
    const int warp = tid >> 5, lane = tid & 31;
    const int wm = warp >> 2, wn = warp & 3;   // 2 x 4 warp grid
    const int g2 = lane >> 2, t4 = lane & 3;
    const int cRow = blockIdx.y, cCol = blockIdx.x;

    const float* Ab = A + (size_t)cRow * 128 * K;
    const float* Bb = B + cCol * 128;

    float c[4][4][4];
    #pragma unroll
    for (int mf = 0; mf < 4; mf++)
        #pragma unroll
        for (int nf = 0; nf < 4; nf++)
            #pragma unroll
            for (int i = 0; i < 4; i++) c[mf][nf][i] = 0.f;

    const int nk = K >> 5;    // BK=32

    // prologue: prefetch stage 0
    {
        float* Ad = sm;
        float* Bd = sm + 128 * GA;
        #pragma unroll
        for (int i = 0; i < 4; i++) {                 // A: 128x32 = 1024 float4
            int idx = tid + i * 256;
            int r = idx >> 3, c4 = (idx & 7) << 2;
            CP16(smem_u32(Ad + r * GA + c4), Ab + (size_t)r * K + c4);
        }
        #pragma unroll
        for (int i = 0; i < 4; i++) {                 // B: 32x128 = 1024 float4
            int idx = tid + i * 256;
            int r = idx >> 5, c4 = (idx & 31) << 2;
            CP16(smem_u32(Bd + r * GB + c4), Bb + (size_t)r * N + c4);
        }
        CP_COMMIT();
    }

    for (int it = 0; it < nk; it++) {
        CP_WAIT0();              // stage `it` is the only group in flight
        __syncthreads();         // + proves all warps done with the other stage

        if (it + 1 < nk) {       // prefetch it+1 into the other stage
            const int k0 = (it + 1) << 5;
            float* Ad = sm + ((it + 1) & 1) * STAGE_F;
            float* Bd = Ad + 128 * GA;
            #pragma unroll
            for (int i = 0; i < 4; i++) {
                int idx = tid + i * 256;
                int r = idx >> 3, c4 = (idx & 7) << 2;
                CP16(smem_u32(Ad + r * GA + c4), Ab + (size_t)r * K + k0 + c4);
            }
            #pragma unroll
            for (int i = 0; i < 4; i++) {
                int idx = tid + i * 256;
                int r = idx >> 5, c4 = (idx & 31) << 2;
                CP16(smem_u32(Bd + r * GB + c4), Bb + (size_t)(k0 + r) * N + c4);
            }
            CP_COMMIT();
        }

        const float* Ac = sm + (it & 1) * STAGE_F;
        const float* Bc = Ac + 128 * GA;

        #pragma unroll
        for (int ks = 0; ks < 4; ks++) {
            const int k = ks * 8;
            uint32_t a[4][4], b[4][2];
            #pragma unroll
            for (int mf = 0; mf < 4; mf++) {
                int r0 = wm * 64 + mf * 16 + g2;
                a[mf][0] = fbits(Ac[r0 * GA + k + t4]);
                a[mf][1] = fbits(Ac[(r0 + 8) * GA + k + t4]);
                a[mf][2] = fbits(Ac[r0 * GA + k + 4 + t4]);
                a[mf][3] = fbits(Ac[(r0 + 8) * GA + k + 4 + t4]);
            }
            #pragma unroll
            for (int nf = 0; nf < 4; nf++) {
                int cc = wn * 32 + nf * 8 + g2;
                b[nf][0] = fbits(Bc[(k + t4) * GB + cc]);
                b[nf][1] = fbits(Bc[(k + 4 + t4) * GB + cc]);
            }
            #pragma unroll
            for (int mf = 0; mf < 4; mf++)
                #pragma unroll
                for (int nf = 0; nf < 4; nf++)
                    mma8(c[mf][nf], a[mf][0], a[mf][1], a[mf][2], a[mf][3],
                         b[nf][0], b[nf][1]);
        }
    }

    #pragma unroll
    for (int nf = 0; nf < 4; nf++) {
        int cc = cCol * 128 + wn * 32 + nf * 8 + t4 * 2;
        float b0 = bias[cc], b1 = bias[cc + 1];
        #pragma unroll
        for (int mf = 0; mf < 4; mf++) {
            int r0 = cRow * 128 + wm * 64 + mf * 16 + g2;
            float v00 = c[mf][nf][0] + b0, v01 = c[mf][nf][1] + b1;
            float v10 = c[mf][nf][2] + b0, v11 = c[mf][nf][3] + b1;
            if (round_out) {
                v00 = tf32f(v00); v01 = tf32f(v01);
                v10 = tf32f(v10); v11 = tf32f(v11);
            }
            *reinterpret_cast<float2*>(C + (size_t)r0 * N + cc)       = make_float2(v00, v01);
            *reinterpret_cast<float2*>(C + (size_t)(r0 + 8) * N + cc) = make_float2(v10, v11);
        }
    }
}

// ---------------------------------------------------------------------------
// TF32 causal flash attention: BQ=128, BKV=64, 256 threads (8 warps).
// Unchanged from R9.
// ---------------------------------------------------------------------------
#define BQ  128
#define BKV 64
#define QS_S 68
#define KS_S 68
#define VS_S 72
#define PS_S 68
#define SCALE_L2E 0.18033688011112042f   // 0.125 * log2(e)
#define FLASH_SMEM ((128*QS_S + 2*64*KS_S + 2*64*VS_S + 128*PS_S) * 4)  // 141312 B

__global__ __launch_bounds__(256, 1) void flash_tf32(
    const float* __restrict__ qkv, float* __restrict__ attn_out)
{
    extern __shared__ float sm[];
    float* Qs = sm;                       // [128][68]
    float* Ks = Qs + 128 * QS_S;          // [2][64][68]
    float* Vs = Ks + 2 * 64 * KS_S;       // [2][64][72]
    float* Ps = Vs + 2 * 64 * VS_S;       // [128][68]

    const int qb = gridDim.x - 1 - blockIdx.x;   // heavy blocks first
    const int h = blockIdx.y, b = blockIdx.z;
    const int tid = threadIdx.x, warp = tid >> 5, lane = tid & 31;
    const int g2 = lane >> 2, t4 = lane & 3;
    const int q0 = qb * BQ;
    const int kr = tid >> 4, kc = (tid & 15) << 2;

    #pragma unroll
    for (int i = 0; i < 8; i++) {
        int idx = tid + i * 256;
        int r = idx >> 4, c4 = (idx & 15) << 2;
        float4 v = *reinterpret_cast<const float4*>(
            qkv + (size_t)(b * SEQ + q0 + r) * 3072 + h * 64 + c4);
        Qs[r * QS_S + c4 + 0] = tf32f(v.x * SCALE_L2E);
        Qs[r * QS_S + c4 + 1] = tf32f(v.y * SCALE_L2E);
        Qs[r * QS_S + c4 + 2] = tf32f(v.z * SCALE_L2E);
        Qs[r * QS_S + c4 + 3] = tf32f(v.w * SCALE_L2E);
    }

    const int r0l = warp * 16 + g2;
    const int grow0 = q0 + r0l, grow1 = grow0 + 8;
    float m0 = -1e30f, m1 = -1e30f, l0 = 0.f, l1 = 0.f;
    float o[8][4];
    #pragma unroll
    for (int nf = 0; nf < 8; nf++)
        #pragma unroll
        for (int i = 0; i < 4; i++) o[nf][i] = 0.f;

    const int nkv = 2 * qb + 2;

    #pragma unroll
    for (int i = 0; i < 4; i++) {
        int r = kr + i * 16;
        size_t base = (size_t)(b * SEQ + r) * 3072 + h * 64 + kc;
        CP16(smem_u32(Ks + r * KS_S + kc), qkv + base + 1024);
        CP16(smem_u32(Vs + r * VS_S + kc), qkv + base + 2048);
    }
    CP_COMMIT();

    for (int t = 0; t < nkv; t++) {
        CP_WAIT0();
        __syncthreads();

        if (t + 1 < nkv) {
            const int kv1 = (t + 1) * BKV;
            float* Kd = Ks + ((t + 1) & 1) * 64 * KS_S;
            float* Vd = Vs + ((t + 1) & 1) * 64 * VS_S;
            #pragma unroll
            for (int i = 0; i < 4; i++) {
                int r = kr + i * 16;
                size_t base = (size_t)(b * SEQ + kv1 + r) * 3072 + h * 64 + kc;
                CP16(smem_u32(Kd + r * KS_S + kc), qkv + base + 1024);
                CP16(smem_u32(Vd + r * VS_S + kc), qkv + base + 2048);
            }
            CP_COMMIT();
        }

        const float* Kc = Ks + (t & 1) * 64 * KS_S;
        const float* Vc = Vs + (t & 1) * 64 * VS_S;

        float s[8][4];
        #pragma unroll
        for (int nf = 0; nf < 8; nf++)
            #pragma unroll
            for (int i = 0; i < 4; i++) s[nf][i] = 0.f;

        #pragma unroll
        for (int ks = 0; ks < 8; ks++) {
            const int k = ks * 8;
            uint32_t a0 = fbits(Qs[r0l * QS_S + k + t4]);
            uint32_t a1 = fbits(Qs[(r0l + 8) * QS_S + k + t4]);
            uint32_t a2 = fbits(Qs[r0l * QS_S + k + 4 + t4]);
            uint32_t a3 = fbits(Qs[(r0l + 8) * QS_S + k + 4 + t4]);
            #pragma unroll
            for (int nf = 0; nf < 8; nf++) {
                int cc = nf * 8 + g2;
                uint32_t b0 = fbits(Kc[cc * KS_S + k + t4]);
                uint32_t b1 = fbits(Kc[cc * KS_S + k + 4 + t4]);
                mma8(s[nf], a0, a1, a2, a3, b0, b1);
            }
        }

        const bool nm = (t >= nkv - 2);
        float mx0 = -1e30f, mx1 = -1e30f;
        #pragma unroll
        for (int nf = 0; nf < 8; nf++) {
            #pragma unroll
            for (int j = 0; j < 2; j++) {
                int gc = t * BKV + nf * 8 + t4 * 2 + j;
                if (nm && gc > grow0) s[nf][j]     = -1e30f;
                if (nm && gc > grow1) s[nf][2 + j] = -1e30f;
                mx0 = fmaxf(mx0, s[nf][j]);
                mx1 = fmaxf(mx1, s[nf][2 + j]);
            }
        }
        mx0 = fmaxf(mx0, __shfl_xor_sync(0xffffffffu, mx0, 1));
        mx0 = fmaxf(mx0, __shfl_xor_sync(0xffffffffu, mx0, 2));
        mx1 = fmaxf(mx1, __shfl_xor_sync(0xffffffffu, mx1, 1));
        mx1 = fmaxf(mx1, __shfl_xor_sync(0xffffffffu, mx1, 2));

        const float mn0 = fmaxf(m0, mx0);
        const float mn1 = fmaxf(m1, mx1);
        const float a0s = ex2(m0 - mn0);
        const float a1s = ex2(m1 - mn1);

        float ps0 = 0.f, ps1 = 0.f;
        #pragma unroll
        for (int nf = 0; nf < 8; nf++) {
            float p00 = ex2(s[nf][0] - mn0);
            float p01 = ex2(s[nf][1] - mn0);
            float p10 = ex2(s[nf][2] - mn1);
            float p11 = ex2(s[nf][3] - mn1);
            ps0 += p00 + p01; ps1 += p10 + p11;
            int cc = nf * 8 + t4 * 2;
            *reinterpret_cast<float2*>(&Ps[r0l * PS_S + cc]) =
                make_float2(tf32f(p00), tf32f(p01));
            *reinterpret_cast<float2*>(&Ps[(r0l + 8) * PS_S + cc]) =
                make_float2(tf32f(p10), tf32f(p11));
        }
        ps0 += __shfl_xor_sync(0xffffffffu, ps0, 1);
        ps0 += __shfl_xor_sync(0xffffffffu, ps0, 2);
        ps1 += __shfl_xor_sync(0xffffffffu, ps1, 1);
        ps1 += __shfl_xor_sync(0xffffffffu, ps1, 2);
        l0 = l0 * a0s + ps0;
        l1 = l1 * a1s + ps1;
        m0 = mn0; m1 = mn1;

        #pragma unroll
        for (int nf = 0; nf < 8; nf++) {
            o[nf][0] *= a0s; o[nf][1] *= a0s;
            o[nf][2] *= a1s; o[nf][3] *= a1s;
        }
        __syncwarp();

        #pragma unroll
        for (int ks = 0; ks < 8; ks++) {
            const int k = ks * 8;
            uint32_t a0 = fbits(Ps[r0l * PS_S + k + t4]);
            uint32_t a1 = fbits(Ps[(r0l + 8) * PS_S + k + t4]);
            uint32_t a2 = fbits(Ps[r0l * PS_S + k + 4 + t4]);
            uint32_t a3 = fbits(Ps[(r0l + 8) * PS_S + k + 4 + t4]);
            #pragma unroll
            for (int nf = 0; nf < 8; nf++) {
                int cc = nf * 8 + g2;
                uint32_t b0 = fbits(Vc[(k + t4) * VS_S + cc]);
                uint32_t b1 = fbits(Vc[(k + 4 + t4) * VS_S + cc]);
                mma8(o[nf], a0, a1, a2, a3, b0, b1);
            }
        }
    }

    const float inv0 = 1.f / l0, inv1 = 1.f / l1;
    #pragma unroll
    for (int nf = 0; nf < 8; nf++) {
        int cc = nf * 8 + t4 * 2;
        float* p0 = attn_out + (size_t)(b * SEQ + grow0) * HID + h * 64 + cc;
        float* p1 = attn_out + (size_t)(b * SEQ + grow1) * HID + h * 64 + cc;
        *reinterpret_cast<float2*>(p0) =
            make_float2(tf32f(o[nf][0] * inv0), tf32f(o[nf][1] * inv0));
        *reinterpret_cast<float2*>(p1) =
            make_float2(tf32f(o[nf][2] * inv1), tf32f(o[nf][3] * inv1));
    }
}

// ---------------------------------------------------------------------------
extern "C" void kernel_launch(void* const* d_in, const int* in_sizes, int n_in,
                              void* d_out, int out_size)
{
    const float* x     = (const float*)d_in[0];
    const float* w_qkv = (const float*)d_in[1];
    const float* b_qkv = (const float*)d_in[2];
    const float* w_out = (const float*)d_in[3];
    const float* b_out = (const float*)d_in[4];
    float* out = (float*)d_out;

    float *qkv, *attn, *xc, *w1, *w2;
    cudaGetSymbolAddress((void**)&qkv,  g_qkv);
    cudaGetSymbolAddress((void**)&attn, g_attn);
    cudaGetSymbolAddress((void**)&xc,   g_xc);
    cudaGetSymbolAddress((void**)&w1,   g_w1);
    cudaGetSymbolAddress((void**)&w2,   g_w2);

    cudaFuncSetAttribute(gemm_tf32,  cudaFuncAttributeMaxDynamicSharedMemorySize, GEMM_SMEM);
    cudaFuncSetAttribute(flash_tf32, cudaFuncAttributeMaxDynamicSharedMemorySize, FLASH_SMEM);

    // 0) round all inputs to tf32 in ONE launch
    round3_kernel<<<(N4_ALL + 255) / 256, 256>>>(x, xc, w_qkv, w1, w_out, w2);

    // 1) qkv = xc @ w1 + b_qkv (output rounded to tf32)
    dim3 g1(3 * HID / 128, NTOK / 128);
    gemm_tf32<<<g1, 256, GEMM_SMEM>>>(xc, w1, b_qkv, qkv, NTOK, 3 * HID, HID, 1);

    // 2) causal flash attention
    dim3 g2(SEQ / BQ, NHEAD, BATCH);
    flash_tf32<<<g2, 256, FLASH_SMEM>>>(qkv, attn);

    // 3) out = attn @ w2 + b_out
    dim3 g3(HID / 128, NTOK / 128);
    gemm_tf32<<<g3, 256, GEMM_SMEM>>>(attn, w2, b_out, out, NTOK, HID, HID, 0);
}

// round 11
// speedup vs baseline: 1.1040x; 1.0260x over previous
#include <cuda_runtime.h>
#include <cstdint>

#define BATCH 2
#define SEQ   2048
#define HID   1024
#define NHEAD 16
#define HDIM  64
#define NTOK  (BATCH*SEQ)

// Scratch (device globals: allocation-free rule)
__device__ float g_qkv[NTOK * 3 * HID];   // (B,S,3,NH,HD) tf32-rounded
__device__ float g_attn[NTOK * HID];      // tf32-rounded
__device__ float g_xc[NTOK * HID];
__device__ float g_w1[HID * 3 * HID];
__device__ float g_w2[HID * HID];

// ---------------------------------------------------------------------------
__device__ __forceinline__ float tf32f(float x) {
    uint32_t u;
    asm("cvt.rna.tf32.f32 %0, %1;" : "=r"(u) : "f"(x));
    return __uint_as_float(u);
}
__device__ __forceinline__ float ex2(float x) {
    float y;
    asm("ex2.approx.ftz.f32 %0, %1;" : "=f"(y) : "f"(x));
    return y;
}
__device__ __forceinline__ uint32_t fbits(float x) { return __float_as_uint(x); }
__device__ __forceinline__ uint32_t smem_u32(const void* p) {
    return (uint32_t)__cvta_generic_to_shared(p);
}
#define CP16(dst_u32, src_ptr) \
    asm volatile("cp.async.ca.shared.global [%0], [%1], 16;" :: "r"(dst_u32), "l"(src_ptr))
#define CP_COMMIT() asm volatile("cp.async.commit_group;")
#define CP_WAIT0()  asm volatile("cp.async.wait_group 0;")

__device__ __forceinline__ void mma8(float* c,
                                     uint32_t a0, uint32_t a1, uint32_t a2, uint32_t a3,
                                     uint32_t b0, uint32_t b1) {
    asm volatile(
        "mma.sync.aligned.m16n8k8.row.col.f32.tf32.tf32.f32 "
        "{%0,%1,%2,%3}, {%4,%5,%6,%7}, {%8,%9}, {%0,%1,%2,%3};"
        : "+f"(c[0]), "+f"(c[1]), "+f"(c[2]), "+f"(c[3])
        : "r"(a0), "r"(a1), "r"(a2), "r"(a3), "r"(b0), "r"(b1));
}

// ---------------------------------------------------------------------------
// Fused tf32 rounding prepass: x -> xc, w_qkv -> w1, w_out -> w2 in ONE launch.
// ---------------------------------------------------------------------------
#define N4_X  (NTOK * HID / 4)          // 1048576
#define N4_W1 (HID * 3 * HID / 4)       // 786432
#define N4_W2 (HID * HID / 4)           // 262144
#define N4_ALL (N4_X + N4_W1 + N4_W2)   // 2097152

__global__ void round3_kernel(const float* __restrict__ x,  float* __restrict__ xc,
                              const float* __restrict__ w1i, float* __restrict__ w1o,
                              const float* __restrict__ w2i, float* __restrict__ w2o)
{
    int i = blockIdx.x * blockDim.x + threadIdx.x;
    const float4* in;
    float4* out;
    int idx;
    if (i < N4_X)              { in = (const float4*)x;   out = (float4*)xc;  idx = i; }
    else if (i < N4_X + N4_W1) { in = (const float4*)w1i; out = (float4*)w1o; idx = i - N4_X; }
    else if (i < N4_ALL)       { in = (const float4*)w2i; out = (float4*)w2o; idx = i - N4_X - N4_W1; }
    else return;
    float4 v = in[idx];
    out[idx] = make_float4(tf32f(v.x), tf32f(v.y), tf32f(v.z), tf32f(v.w));
}

// ---------------------------------------------------------------------------
// TF32 GEMM: 128x256x32 CTA tile, 256 threads (8 warps, 2x4 grid, 64x64 warp
// tiles), 2-stage cp.async, 1 barrier/iter. Higher math-per-byte:
// 3072 float4 loaded per 1024 SM-mma (was 2048 per 512).
// ---------------------------------------------------------------------------
#define GA 36
#define GB 260
#define STAGE_F (128*GA + 32*GB)               // 12928 floats
#define GEMM_SMEM (2 * STAGE_F * 4)            // 103424 B

__global__ __launch_bounds__(256, 1) void gemm_tf32(
    const float* __restrict__ A, const float* __restrict__ B,
    const float* __restrict__ bias, float* __restrict__ C,
    int M, int N, int K, int round_out)
{
    extern __shared__ float sm[];

    const int tid  = threadIdx.x;
    const int warp = tid >> 5, lane = tid & 31;
    const int wm = warp >> 2, wn = warp & 3;   // 2 x 4 warp grid -> 64x64 tiles
    const int g2 = lane >> 2, t4 = lane & 3;
    const int cRow = blockIdx.y, cCol = blockIdx.x;

    const float* Ab = A + (size_t)cRow * 128 * K;
    const float* Bb = B + cCol * 256;

    float c[4][8][4];
    #pragma unroll
    for (int mf = 0; mf < 4; mf++)
        #pragma unroll
        for (int nf = 0; nf < 8; nf++)
            #pragma unroll
            for (int i = 0; i < 4; i++) c[mf][nf][i] = 0.f;

    const int nk = K >> 5;    // BK=32

    // prologue: prefetch stage 0
    {
        float* Ad = sm;
        float* Bd = sm + 128 * GA;
        #pragma unroll
        for (int i = 0; i < 4; i++) {                 // A: 128x32 = 1024 float4
            int idx = tid + i * 256;
            int r = idx >> 3, c4 = (idx & 7) << 2;
            CP16(smem_u32(Ad + r * GA + c4), Ab + (size_t)r * K + c4);
        }
        #pragma unroll
        for (int i = 0; i < 8; i++) {                 // B: 32x256 = 2048 float4
            int idx = tid + i * 256;
            int r = idx >> 6, c4 = (idx & 63) << 2;
            CP16(smem_u32(Bd + r * GB + c4), Bb + (size_t)r * N + c4);
        }
        CP_COMMIT();
    }

    for (int it = 0; it < nk; it++) {
        CP_WAIT0();              // stage `it` is the only group in flight
        __syncthreads();         // + proves all warps done with the other stage

        if (it + 1 < nk) {       // prefetch it+1 into the other stage
            const int k0 = (it + 1) << 5;
            float* Ad = sm + ((it + 1) & 1) * STAGE_F;
            float* Bd = Ad + 128 * GA;
            #pragma unroll
            for (int i = 0; i < 4; i++) {
                int idx = tid + i * 256;
                int r = idx >> 3, c4 = (idx & 7) << 2;
                CP16(smem_u32(Ad + r * GA + c4), Ab + (size_t)r * K + k0 + c4);
            }
            #pragma unroll
            for (int i = 0; i < 8; i++) {
                int idx = tid + i * 256;
                int r = idx >> 6, c4 = (idx & 63) << 2;
                CP16(smem_u32(Bd + r * GB + c4), Bb + (size_t)(k0 + r) * N + c4);
            }
            CP_COMMIT();
        }

        const float* Ac = sm + (it & 1) * STAGE_F;
        const float* Bc = Ac + 128 * GA;

        #pragma unroll
        for (int ks = 0; ks < 4; ks++) {
            const int k = ks * 8;
            uint32_t a[4][4], b[8][2];
            #pragma unroll
            for (int mf = 0; mf < 4; mf++) {
                int r0 = wm * 64 + mf * 16 + g2;
                a[mf][0] = fbits(Ac[r0 * GA + k + t4]);
                a[mf][1] = fbits(Ac[(r0 + 8) * GA + k + t4]);
                a[mf][2] = fbits(Ac[r0 * GA + k + 4 + t4]);
                a[mf][3] = fbits(Ac[(r0 + 8) * GA + k + 4 + t4]);
            }
            #pragma unroll
            for (int nf = 0; nf < 8; nf++) {
                int cc = wn * 64 + nf * 8 + g2;
                b[nf][0] = fbits(Bc[(k + t4) * GB + cc]);
                b[nf][1] = fbits(Bc[(k + 4 + t4) * GB + cc]);
            }
            #pragma unroll
            for (int mf = 0; mf < 4; mf++)
                #pragma unroll
                for (int nf = 0; nf < 8; nf++)
                    mma8(c[mf][nf], a[mf][0], a[mf][1], a[mf][2], a[mf][3],
                         b[nf][0], b[nf][1]);
        }
    }

    #pragma unroll
    for (int nf = 0; nf < 8; nf++) {
        int cc = cCol * 256 + wn * 64 + nf * 8 + t4 * 2;
        float b0 = bias[cc], b1 = bias[cc + 1];
        #pragma unroll
        for (int mf = 0; mf < 4; mf++) {
            int r0 = cRow * 128 + wm * 64 + mf * 16 + g2;
            float v00 = c[mf][nf][0] + b0, v01 = c[mf][nf][1] + b1;
            float v10 = c[mf][nf][2] + b0, v11 = c[mf][nf][3] + b1;
            if (round_out) {
                v00 = tf32f(v00); v01 = tf32f(v01);
                v10 = tf32f(v10); v11 = tf32f(v11);
            }
            *reinterpret_cast<float2*>(C + (size_t)r0 * N + cc)       = make_float2(v00, v01);
            *reinterpret_cast<float2*>(C + (size_t)(r0 + 8) * N + cc) = make_float2(v10, v11);
        }
    }
}

// ---------------------------------------------------------------------------
// TF32 causal flash attention: BQ=128, BKV=64, 256 threads (8 warps).
// Unchanged from R10.
// ---------------------------------------------------------------------------
#define BQ  128
#define BKV 64
#define QS_S 68
#define KS_S 68
#define VS_S 72
#define PS_S 68
#define SCALE_L2E 0.18033688011112042f   // 0.125 * log2(e)
#define FLASH_SMEM ((128*QS_S + 2*64*KS_S + 2*64*VS_S + 128*PS_S) * 4)  // 141312 B

__global__ __launch_bounds__(256, 1) void flash_tf32(
    const float* __restrict__ qkv, float* __restrict__ attn_out)
{
    extern __shared__ float sm[];
    float* Qs = sm;                       // [128][68]
    float* Ks = Qs + 128 * QS_S;          // [2][64][68]
    float* Vs = Ks + 2 * 64 * KS_S;       // [2][64][72]
    float* Ps = Vs + 2 * 64 * VS_S;       // [128][68]

    const int qb = gridDim.x - 1 - blockIdx.x;   // heavy blocks first
    const int h = blockIdx.y, b = blockIdx.z;
    const int tid = threadIdx.x, warp = tid >> 5, lane = tid & 31;
    const int g2 = lane >> 2, t4 = lane & 3;
    const int q0 = qb * BQ;
    const int kr = tid >> 4, kc = (tid & 15) << 2;

    #pragma unroll
    for (int i = 0; i < 8; i++) {
        int idx = tid + i * 256;
        int r = idx >> 4, c4 = (idx & 15) << 2;
        float4 v = *reinterpret_cast<const float4*>(
            qkv + (size_t)(b * SEQ + q0 + r) * 3072 + h * 64 + c4);
        Qs[r * QS_S + c4 + 0] = tf32f(v.x * SCALE_L2E);
        Qs[r * QS_S + c4 + 1] = tf32f(v.y * SCALE_L2E);
        Qs[r * QS_S + c4 + 2] = tf32f(v.z * SCALE_L2E);
        Qs[r * QS_S + c4 + 3] = tf32f(v.w * SCALE_L2E);
    }

    const int r0l = warp * 16 + g2;
    const int grow0 = q0 + r0l, grow1 = grow0 + 8;
    float m0 = -1e30f, m1 = -1e30f, l0 = 0.f, l1 = 0.f;
    float o[8][4];
    #pragma unroll
    for (int nf = 0; nf < 8; nf++)
        #pragma unroll
        for (int i = 0; i < 4; i++) o[nf][i] = 0.f;

    const int nkv = 2 * qb + 2;

    #pragma unroll
    for (int i = 0; i < 4; i++) {
        int r = kr + i * 16;
        size_t base = (size_t)(b * SEQ + r) * 3072 + h * 64 + kc;
        CP16(smem_u32(Ks + r * KS_S + kc), qkv + base + 1024);
        CP16(smem_u32(Vs + r * VS_S + kc), qkv + base + 2048);
    }
    CP_COMMIT();

    for (int t = 0; t < nkv; t++) {
        CP_WAIT0();
        __syncthreads();

        if (t + 1 < nkv) {
            const int kv1 = (t + 1) * BKV;
            float* Kd = Ks + ((t + 1) & 1) * 64 * KS_S;
            float* Vd = Vs + ((t + 1) & 1) * 64 * VS_S;
            #pragma unroll
            for (int i = 0; i < 4; i++) {
                int r = kr + i * 16;
                size_t base = (size_t)(b * SEQ + kv1 + r) * 3072 + h * 64 + kc;
                CP16(smem_u32(Kd + r * KS_S + kc), qkv + base + 1024);
                CP16(smem_u32(Vd + r * VS_S + kc), qkv + base + 2048);
            }
            CP_COMMIT();
        }

        const float* Kc = Ks + (t & 1) * 64 * KS_S;
        const float* Vc = Vs + (t & 1) * 64 * VS_S;

        float s[8][4];
        #pragma unroll
        for (int nf = 0; nf < 8; nf++)
            #pragma unroll
            for (int i = 0; i < 4; i++) s[nf][i] = 0.f;

        #pragma unroll
        for (int ks = 0; ks < 8; ks++) {
            const int k = ks * 8;
            uint32_t a0 = fbits(Qs[r0l * QS_S + k + t4]);
            uint32_t a1 = fbits(Qs[(r0l + 8) * QS_S + k + t4]);
            uint32_t a2 = fbits(Qs[r0l * QS_S + k + 4 + t4]);
            uint32_t a3 = fbits(Qs[(r0l + 8) * QS_S + k + 4 + t4]);
            #pragma unroll
            for (int nf = 0; nf < 8; nf++) {
                int cc = nf * 8 + g2;
                uint32_t b0 = fbits(Kc[cc * KS_S + k + t4]);
                uint32_t b1 = fbits(Kc[cc * KS_S + k + 4 + t4]);
                mma8(s[nf], a0, a1, a2, a3, b0, b1);
            }
        }

        const bool nm = (t >= nkv - 2);
        float mx0 = -1e30f, mx1 = -1e30f;
        #pragma unroll
        for (int nf = 0; nf < 8; nf++) {
            #pragma unroll
            for (int j = 0; j < 2; j++) {
                int gc = t * BKV + nf * 8 + t4 * 2 + j;
                if (nm && gc > grow0) s[nf][j]     = -1e30f;
                if (nm && gc > grow1) s[nf][2 + j] = -1e30f;
                mx0 = fmaxf(mx0, s[nf][j]);
                mx1 = fmaxf(mx1, s[nf][2 + j]);
            }
        }
        mx0 = fmaxf(mx0, __shfl_xor_sync(0xffffffffu, mx0, 1));
        mx0 = fmaxf(mx0, __shfl_xor_sync(0xffffffffu, mx0, 2));
        mx1 = fmaxf(mx1, __shfl_xor_sync(0xffffffffu, mx1, 1));
        mx1 = fmaxf(mx1, __shfl_xor_sync(0xffffffffu, mx1, 2));

        const float mn0 = fmaxf(m0, mx0);
        const float mn1 = fmaxf(m1, mx1);
        const float a0s = ex2(m0 - mn0);
        const float a1s = ex2(m1 - mn1);

        float ps0 = 0.f, ps1 = 0.f;
        #pragma unroll
        for (int nf = 0; nf < 8; nf++) {
            float p00 = ex2(s[nf][0] - mn0);
            float p01 = ex2(s[nf][1] - mn0);
            float p10 = ex2(s[nf][2] - mn1);
            float p11 = ex2(s[nf][3] - mn1);
            ps0 += p00 + p01; ps1 += p10 + p11;
            int cc = nf * 8 + t4 * 2;
            *reinterpret_cast<float2*>(&Ps[r0l * PS_S + cc]) =
                make_float2(tf32f(p00), tf32f(p01));
            *reinterpret_cast<float2*>(&Ps[(r0l + 8) * PS_S + cc]) =
                make_float2(tf32f(p10), tf32f(p11));
        }
        ps0 += __shfl_xor_sync(0xffffffffu, ps0, 1);
        ps0 += __shfl_xor_sync(0xffffffffu, ps0, 2);
        ps1 += __shfl_xor_sync(0xffffffffu, ps1, 1);
        ps1 += __shfl_xor_sync(0xffffffffu, ps1, 2);
        l0 = l0 * a0s + ps0;
        l1 = l1 * a1s + ps1;
        m0 = mn0; m1 = mn1;

        #pragma unroll
        for (int nf = 0; nf < 8; nf++) {
            o[nf][0] *= a0s; o[nf][1] *= a0s;
            o[nf][2] *= a1s; o[nf][3] *= a1s;
        }
        __syncwarp();

        #pragma unroll
        for (int ks = 0; ks < 8; ks++) {
            const int k = ks * 8;
            uint32_t a0 = fbits(Ps[r0l * PS_S + k + t4]);
            uint32_t a1 = fbits(Ps[(r0l + 8) * PS_S + k + t4]);
            uint32_t a2 = fbits(Ps[r0l * PS_S + k + 4 + t4]);
            uint32_t a3 = fbits(Ps[(r0l + 8) * PS_S + k + 4 + t4]);
            #pragma unroll
            for (int nf = 0; nf < 8; nf++) {
                int cc = nf * 8 + g2;
                uint32_t b0 = fbits(Vc[(k + t4) * VS_S + cc]);
                uint32_t b1 = fbits(Vc[(k + 4 + t4) * VS_S + cc]);
                mma8(o[nf], a0, a1, a2, a3, b0, b1);
            }
        }
    }

    const float inv0 = 1.f / l0, inv1 = 1.f / l1;
    #pragma unroll
    for (int nf = 0; nf < 8; nf++) {
        int cc = nf * 8 + t4 * 2;
        float* p0 = attn_out + (size_t)(b * SEQ + grow0) * HID + h * 64 + cc;
        float* p1 = attn_out + (size_t)(b * SEQ + grow1) * HID + h * 64 + cc;
        *reinterpret_cast<float2*>(p0) =
            make_float2(tf32f(o[nf][0] * inv0), tf32f(o[nf][1] * inv0));
        *reinterpret_cast<float2*>(p1) =
            make_float2(tf32f(o[nf][2] * inv1), tf32f(o[nf][3] * inv1));
    }
}

// ---------------------------------------------------------------------------
extern "C" void kernel_launch(void* const* d_in, const int* in_sizes, int n_in,
                              void* d_out, int out_size)
{
    const float* x     = (const float*)d_in[0];
    const float* w_qkv = (const float*)d_in[1];
    const float* b_qkv = (const float*)d_in[2];
    const float* w_out = (const float*)d_in[3];
    const float* b_out = (const float*)d_in[4];
    float* out = (float*)d_out;

    float *qkv, *attn, *xc, *w1, *w2;
    cudaGetSymbolAddress((void**)&qkv,  g_qkv);
    cudaGetSymbolAddress((void**)&attn, g_attn);
    cudaGetSymbolAddress((void**)&xc,   g_xc);
    cudaGetSymbolAddress((void**)&w1,   g_w1);
    cudaGetSymbolAddress((void**)&w2,   g_w2);

    cudaFuncSetAttribute(gemm_tf32,  cudaFuncAttributeMaxDynamicSharedMemorySize, GEMM_SMEM);
    cudaFuncSetAttribute(flash_tf32, cudaFuncAttributeMaxDynamicSharedMemorySize, FLASH_SMEM);

    // 0) round all inputs to tf32 in ONE launch
    round3_kernel<<<(N4_ALL + 255) / 256, 256>>>(x, xc, w_qkv, w1, w_out, w2);

    // 1) qkv = xc @ w1 + b_qkv (output rounded to tf32)
    dim3 g1(3 * HID / 256, NTOK / 128);
    gemm_tf32<<<g1, 256, GEMM_SMEM>>>(xc, w1, b_qkv, qkv, NTOK, 3 * HID, HID, 1);

    // 2) causal flash attention
    dim3 g2(SEQ / BQ, NHEAD, BATCH);
    flash_tf32<<<g2, 256, FLASH_SMEM>>>(qkv, attn);

    // 3) out = attn @ w2 + b_out
    dim3 g3(HID / 256, NTOK / 128);
    gemm_tf32<<<g3, 256, GEMM_SMEM>>>(attn, w2, b_out, out, NTOK, HID, HID, 0);
}

// round 13
// speedup vs baseline: 1.9467x; 1.7634x over previous
#include <cuda_runtime.h>
#include <cuda_fp16.h>
#include <cstdint>

#define BATCH 2
#define SEQ   2048
#define HID   1024
#define NHEAD 16
#define HDIM  64
#define NTOK  (BATCH*SEQ)

// ---------------- device scratch (allocation-free rule) ----------------
__device__ __half g_xh   [NTOK * HID];          // x fp16 [M][K]
__device__ __half g_w1t  [3 * HID * HID];       // w_qkv^T fp16 [N=3072][K=1024]
__device__ __half g_w2t  [HID * HID];           // w_out^T fp16 [N=1024][K=1024]
__device__ __half g_qkvh [NTOK * 2 * HID];      // Q,K halves fp16 [tok][2048]
__device__ __half g_vt   [BATCH * NHEAD * HDIM * SEQ];  // V^T fp16 [(b,h,d)][s]
__device__ __half g_attnh[NTOK * HID];          // attn out fp16 [tok][1024]

// ---------------------------------------------------------------------------
__device__ __forceinline__ float ex2(float x) {
    float y;
    asm("ex2.approx.ftz.f32 %0, %1;" : "=f"(y) : "f"(x));
    return y;
}
__device__ __forceinline__ uint32_t smem_u32(const void* p) {
    return (uint32_t)__cvta_generic_to_shared(p);
}
#define CP16(dst_u32, src_ptr) \
    asm volatile("cp.async.ca.shared.global [%0], [%1], 16;" :: "r"(dst_u32), "l"(src_ptr))
#define CP_COMMIT() asm volatile("cp.async.commit_group;")
#define CP_WAIT0()  asm volatile("cp.async.wait_group 0;")

// fp16 mma: D(f32) = A(f16) * B(f16) + D, m16n8k16
__device__ __forceinline__ void mma16(float* c,
                                      uint32_t a0, uint32_t a1, uint32_t a2, uint32_t a3,
                                      uint32_t b0, uint32_t b1) {
    asm volatile(
        "mma.sync.aligned.m16n8k16.row.col.f32.f16.f16.f32 "
        "{%0,%1,%2,%3}, {%4,%5,%6,%7}, {%8,%9}, {%0,%1,%2,%3};"
        : "+f"(c[0]), "+f"(c[1]), "+f"(c[2]), "+f"(c[3])
        : "r"(a0), "r"(a1), "r"(a2), "r"(a3), "r"(b0), "r"(b1));
}
__device__ __forceinline__ uint32_t ldh2(const __half* p) {
    return *reinterpret_cast<const uint32_t*>(p);
}

// ---------------------------------------------------------------------------
// prepass 1: x fp32 -> fp16
// ---------------------------------------------------------------------------
__global__ void conv_h_kernel(const float* __restrict__ in, __half* __restrict__ out, int n4)
{
    int i = blockIdx.x * blockDim.x + threadIdx.x;
    if (i >= n4) return;
    float4 v = reinterpret_cast<const float4*>(in)[i];
    __half2 h0 = __float22half2_rn(make_float2(v.x, v.y));
    __half2 h1 = __float22half2_rn(make_float2(v.z, v.w));
    reinterpret_cast<uint2*>(out)[i] =
        make_uint2(*reinterpret_cast<uint32_t*>(&h0), *reinterpret_cast<uint32_t*>(&h1));
}

// prepass 2: w fp32 [K][N] -> fp16 [N][K] (transpose)
__global__ void transpose_h_kernel(const float* __restrict__ in, __half* __restrict__ out,
                                   int K, int N)
{
    __shared__ float t[32][33];
    const int n0 = blockIdx.x * 32, k0 = blockIdx.y * 32;
    const int tx = threadIdx.x & 31, ty = threadIdx.x >> 5;   // 32 x 8
    #pragma unroll
    for (int i = 0; i < 4; i++)
        t[ty + i * 8][tx] = in[(size_t)(k0 + ty + i * 8) * N + n0 + tx];
    __syncthreads();
    #pragma unroll
    for (int i = 0; i < 4; i++)
        out[(size_t)(n0 + ty + i * 8) * K + k0 + tx] = __float2half_rn(t[tx][ty + i * 8]);
}

// ---------------------------------------------------------------------------
// FP16 GEMM: C[M,N] = A[M,K](f16,K-major) x Bt[N,K](f16,K-major) + bias.
// CTA tile 128x256, BK=64, 256 threads (8 warps 2x4, 64x64 warp tiles),
// 2-stage cp.async, 1 barrier/iter.
// mode 0: write fp32 C. mode 1 (qkv): cols<2048 -> Ch fp16; cols>=2048 -> vt
// transposed fp16.
// ---------------------------------------------------------------------------
#define GAH 72
#define GBH 72
#define STAGE_H (128*GAH + 256*GBH)            // halfs per stage = 27648
#define GEMM_SMEM (2 * STAGE_H * 2)            // 110592 B

__global__ __launch_bounds__(256, 1) void gemm_h(
    const __half* __restrict__ A, const __half* __restrict__ Bt,
    const float* __restrict__ bias,
    float* __restrict__ Cf, __half* __restrict__ Ch, __half* __restrict__ vt,
    int M, int N, int K, int mode)
{
    extern __shared__ __half smh[];

    const int tid  = threadIdx.x;
    const int warp = tid >> 5, lane = tid & 31;
    const int wm = warp >> 2, wn = warp & 3;   // 2 x 4 warp grid -> 64x64 tiles
    const int g2 = lane >> 2, t4 = lane & 3;
    const int cRow = blockIdx.y, cCol = blockIdx.x;

    const __half* Ab = A + (size_t)cRow * 128 * K;
    const __half* Bb = Bt + (size_t)cCol * 256 * K;

    float c[4][8][4];
    #pragma unroll
    for (int mf = 0; mf < 4; mf++)
        #pragma unroll
        for (int nf = 0; nf < 8; nf++)
            #pragma unroll
            for (int i = 0; i < 4; i++) c[mf][nf][i] = 0.f;

    const int nk = K >> 6;    // BK=64

    // prologue: prefetch stage 0
    {
        __half* Ad = smh;
        __half* Bd = smh + 128 * GAH;
        #pragma unroll
        for (int i = 0; i < 4; i++) {                 // A: 128 rows x 8 pieces
            int idx = tid + i * 256;
            int r = idx >> 3, p = idx & 7;
            CP16(smem_u32(Ad + r * GAH + p * 8), Ab + (size_t)r * K + p * 8);
        }
        #pragma unroll
        for (int i = 0; i < 8; i++) {                 // B: 256 rows x 8 pieces
            int idx = tid + i * 256;
            int r = idx >> 3, p = idx & 7;
            CP16(smem_u32(Bd + r * GBH + p * 8), Bb + (size_t)r * K + p * 8);
        }
        CP_COMMIT();
    }

    for (int it = 0; it < nk; it++) {
        CP_WAIT0();
        __syncthreads();

        if (it + 1 < nk) {
            const int k0 = (it + 1) << 6;
            __half* Ad = smh + ((it + 1) & 1) * STAGE_H;
            __half* Bd = Ad + 128 * GAH;
            #pragma unroll
            for (int i = 0; i < 4; i++) {
                int idx = tid + i * 256;
                int r = idx >> 3, p = idx & 7;
                CP16(smem_u32(Ad + r * GAH + p * 8), Ab + (size_t)r * K + k0 + p * 8);
            }
            #pragma unroll
            for (int i = 0; i < 8; i++) {
                int idx = tid + i * 256;
                int r = idx >> 3, p = idx & 7;
                CP16(smem_u32(Bd + r * GBH + p * 8), Bb + (size_t)r * K + k0 + p * 8);
            }
            CP_COMMIT();
        }

        const __half* Ac = smh + (it & 1) * STAGE_H;
        const __half* Bc = Ac + 128 * GAH;

        #pragma unroll
        for (int ks = 0; ks < 4; ks++) {          // 4 x k16 = BK 64
            const int k = ks * 16;
            uint32_t a[4][4], b[8][2];
            #pragma unroll
            for (int mf = 0; mf < 4; mf++) {
                int r0 = wm * 64 + mf * 16 + g2;
                a[mf][0] = ldh2(Ac + r0 * GAH + k + 2 * t4);
                a[mf][1] = ldh2(Ac + (r0 + 8) * GAH + k + 2 * t4);
                a[mf][2] = ldh2(Ac + r0 * GAH + k + 2 * t4 + 8);
                a[mf][3] = ldh2(Ac + (r0 + 8) * GAH + k + 2 * t4 + 8);
            }
            #pragma unroll
            for (int nf = 0; nf < 8; nf++) {
                int cc = wn * 64 + nf * 8 + g2;
                b[nf][0] = ldh2(Bc + cc * GBH + k + 2 * t4);
                b[nf][1] = ldh2(Bc + cc * GBH + k + 2 * t4 + 8);
            }
            #pragma unroll
            for (int mf = 0; mf < 4; mf++)
                #pragma unroll
                for (int nf = 0; nf < 8; nf++)
                    mma16(c[mf][nf], a[mf][0], a[mf][1], a[mf][2], a[mf][3],
                          b[nf][0], b[nf][1]);
        }
    }

    // epilogue
    #pragma unroll
    for (int nf = 0; nf < 8; nf++) {
        int col = cCol * 256 + wn * 64 + nf * 8 + t4 * 2;
        float b0 = bias[col], b1 = bias[col + 1];
        #pragma unroll
        for (int mf = 0; mf < 4; mf++) {
            int r0 = cRow * 128 + wm * 64 + mf * 16 + g2;
            float v00 = c[mf][nf][0] + b0, v01 = c[mf][nf][1] + b1;
            float v10 = c[mf][nf][2] + b0, v11 = c[mf][nf][3] + b1;
            if (mode == 0) {
                *reinterpret_cast<float2*>(Cf + (size_t)r0 * N + col)       = make_float2(v00, v01);
                *reinterpret_cast<float2*>(Cf + (size_t)(r0 + 8) * N + col) = make_float2(v10, v11);
            } else {
                if (col < 2048) {     // Q,K -> qkvh fp16 [tok][2048]
                    __half2 h0 = __float22half2_rn(make_float2(v00, v01));
                    __half2 h1 = __float22half2_rn(make_float2(v10, v11));
                    *reinterpret_cast<__half2*>(Ch + (size_t)r0 * 2048 + col)       = h0;
                    *reinterpret_cast<__half2*>(Ch + (size_t)(r0 + 8) * 2048 + col) = h1;
                } else {              // V -> vt transposed [(b,h,d)][s]
                    int hh = (col - 2048) >> 6, d = (col - 2048) & 63;
                    int b0i = r0 >> 11, s0 = r0 & 2047;
                    int b1i = (r0 + 8) >> 11, s1 = (r0 + 8) & 2047;
                    size_t base0 = ((size_t)(b0i * NHEAD + hh) * HDIM + d) * SEQ;
                    size_t base1 = ((size_t)(b1i * NHEAD + hh) * HDIM + d) * SEQ;
                    vt[base0 + s0]       = __float2half_rn(v00);
                    vt[base0 + SEQ + s0] = __float2half_rn(v01);
                    vt[base1 + s1]       = __float2half_rn(v10);
                    vt[base1 + SEQ + s1] = __float2half_rn(v11);
                }
            }
        }
    }
}

// ---------------------------------------------------------------------------
// FP16 causal flash attention: BQ=128, BKV=64, 256 threads (8 warps).
// Q,K from qkvh [tok][2048]; V from vt [(b,h,d)][s] (K-major for PV mma).
// fp32 accum + fp32 softmax; P stored fp16.
// ---------------------------------------------------------------------------
#define BQ  128
#define BKV 64
#define QH_S 72
#define KH_S 72
#define VH_S 72
#define PH_S 72
#define SCALE_L2E 0.18033688011112042f   // 0.125 * log2(e)
#define FLASH_SMEM ((128*QH_S + 2*64*KH_S + 2*64*VH_S + 128*PH_S) * 2)  // 73728 B

__global__ __launch_bounds__(256, 1) void flash_h(
    const __half* __restrict__ qkvh, const __half* __restrict__ vt,
    __half* __restrict__ attn_out)
{
    extern __shared__ __half smh[];
    __half* Qs  = smh;                      // [128][72]
    __half* Ks  = Qs + 128 * QH_S;          // [2][64][72]
    __half* Vst = Ks + 2 * 64 * KH_S;       // [2][64][72]  (Vst[d][kv])
    __half* Ps  = Vst + 2 * 64 * VH_S;      // [128][72]

    const int qb = gridDim.x - 1 - blockIdx.x;   // heavy blocks first
    const int h = blockIdx.y, b = blockIdx.z;
    const int tid = threadIdx.x, warp = tid >> 5, lane = tid & 31;
    const int g2 = lane >> 2, t4 = lane & 3;
    const int q0 = qb * BQ;
    const size_t vtbase = (size_t)(b * NHEAD + h) * HDIM * SEQ;

    // Q tile: 128x64 fp16, scaled by 0.125*log2e
    {
        const __half2 sc2 = __float2half2_rn(SCALE_L2E);
        #pragma unroll
        for (int i = 0; i < 4; i++) {
            int idx = tid + i * 256;              // 1024 chunks of 8 halfs
            int r = idx >> 3, p = idx & 7;
            const __half2* src = reinterpret_cast<const __half2*>(
                qkvh + (size_t)(b * SEQ + q0 + r) * 2048 + h * 64 + p * 8);
            __half2* dst = reinterpret_cast<__half2*>(Qs + r * QH_S + p * 8);
            dst[0] = __hmul2(src[0], sc2);
            dst[1] = __hmul2(src[1], sc2);
            dst[2] = __hmul2(src[2], sc2);
            dst[3] = __hmul2(src[3], sc2);
        }
    }

    const int r0l = warp * 16 + g2;
    const int grow0 = q0 + r0l, grow1 = grow0 + 8;
    float m0 = -1e30f, m1 = -1e30f, l0 = 0.f, l1 = 0.f;
    float o[8][4];
    #pragma unroll
    for (int nf = 0; nf < 8; nf++)
        #pragma unroll
        for (int i = 0; i < 4; i++) o[nf][i] = 0.f;

    const int nkv = 2 * qb + 2;

    // prefetch KV tile 0 (stage 0): K rows [kv][hd], Vt rows [d][kv]
    #pragma unroll
    for (int i = 0; i < 2; i++) {
        int idx = tid + i * 256;                  // 512 chunks: K
        int r = idx >> 3, p = idx & 7;
        CP16(smem_u32(Ks + r * KH_S + p * 8),
             qkvh + (size_t)(b * SEQ + r) * 2048 + 1024 + h * 64 + p * 8);
    }
    #pragma unroll
    for (int i = 0; i < 2; i++) {
        int idx = tid + i * 256;                  // 512 chunks: Vt
        int r = idx >> 3, p = idx & 7;            // r = dim, p*8 = kv offset
        CP16(smem_u32(Vst + r * VH_S + p * 8), vt + vtbase + (size_t)r * SEQ + p * 8);
    }
    CP_COMMIT();

    for (int t = 0; t < nkv; t++) {
        CP_WAIT0();
        __syncthreads();

        if (t + 1 < nkv) {
            const int kv1 = (t + 1) * BKV;
            __half* Kd = Ks + ((t + 1) & 1) * 64 * KH_S;
            __half* Vd = Vst + ((t + 1) & 1) * 64 * VH_S;
            #pragma unroll
            for (int i = 0; i < 2; i++) {
                int idx = tid + i * 256;
                int r = idx >> 3, p = idx & 7;
                CP16(smem_u32(Kd + r * KH_S + p * 8),
                     qkvh + (size_t)(b * SEQ + kv1 + r) * 2048 + 1024 + h * 64 + p * 8);
            }
            #pragma unroll
            for (int i = 0; i < 2; i++) {
                int idx = tid + i * 256;
                int r = idx >> 3, p = idx & 7;
                CP16(smem_u32(Vd + r * VH_S + p * 8),
                     vt + vtbase + (size_t)r * SEQ + kv1 + p * 8);
            }
            CP_COMMIT();
        }

        const __half* Kc = Ks + (t & 1) * 64 * KH_S;
        const __half* Vc = Vst + (t & 1) * 64 * VH_S;

        // ---- S = Qs @ K^T (log2 units), 4 x k16 ----
        float s[8][4];
        #pragma unroll
        for (int nf = 0; nf < 8; nf++)
            #pragma unroll
            for (int i = 0; i < 4; i++) s[nf][i] = 0.f;

        #pragma unroll
        for (int ks = 0; ks < 4; ks++) {
            const int k = ks * 16;
            uint32_t a0 = ldh2(Qs + r0l * QH_S + k + 2 * t4);
            uint32_t a1 = ldh2(Qs + (r0l + 8) * QH_S + k + 2 * t4);
            uint32_t a2 = ldh2(Qs + r0l * QH_S + k + 2 * t4 + 8);
            uint32_t a3 = ldh2(Qs + (r0l + 8) * QH_S + k + 2 * t4 + 8);
            #pragma unroll
            for (int nf = 0; nf < 8; nf++) {
                int cc = nf * 8 + g2;
                uint32_t b0 = ldh2(Kc + cc * KH_S + k + 2 * t4);
                uint32_t b1 = ldh2(Kc + cc * KH_S + k + 2 * t4 + 8);
                mma16(s[nf], a0, a1, a2, a3, b0, b1);
            }
        }

        // ---- mask + quad row max ----
        const bool nm = (t >= nkv - 2);
        float mx0 = -1e30f, mx1 = -1e30f;
        #pragma unroll
        for (int nf = 0; nf < 8; nf++) {
            #pragma unroll
            for (int j = 0; j < 2; j++) {
                int gc = t * BKV + nf * 8 + t4 * 2 + j;
                if (nm && gc > grow0) s[nf][j]     = -1e30f;
                if (nm && gc > grow1) s[nf][2 + j] = -1e30f;
                mx0 = fmaxf(mx0, s[nf][j]);
                mx1 = fmaxf(mx1, s[nf][2 + j]);
            }
        }
        mx0 = fmaxf(mx0, __shfl_xor_sync(0xffffffffu, mx0, 1));
        mx0 = fmaxf(mx0, __shfl_xor_sync(0xffffffffu, mx0, 2));
        mx1 = fmaxf(mx1, __shfl_xor_sync(0xffffffffu, mx1, 1));
        mx1 = fmaxf(mx1, __shfl_xor_sync(0xffffffffu, mx1, 2));

        const float mn0 = fmaxf(m0, mx0);
        const float mn1 = fmaxf(m1, mx1);
        const float a0s = ex2(m0 - mn0);
        const float a1s = ex2(m1 - mn1);

        float ps0 = 0.f, ps1 = 0.f;
        #pragma unroll
        for (int nf = 0; nf < 8; nf++) {
            float p00 = ex2(s[nf][0] - mn0);
            float p01 = ex2(s[nf][1] - mn0);
            float p10 = ex2(s[nf][2] - mn1);
            float p11 = ex2(s[nf][3] - mn1);
            ps0 += p00 + p01; ps1 += p10 + p11;
            int cc = nf * 8 + t4 * 2;
            *reinterpret_cast<__half2*>(Ps + r0l * PH_S + cc) =
                __float22half2_rn(make_float2(p00, p01));
            *reinterpret_cast<__half2*>(Ps + (r0l + 8) * PH_S + cc) =
                __float22half2_rn(make_float2(p10, p11));
        }
        ps0 += __shfl_xor_sync(0xffffffffu, ps0, 1);
        ps0 += __shfl_xor_sync(0xffffffffu, ps0, 2);
        ps1 += __shfl_xor_sync(0xffffffffu, ps1, 1);
        ps1 += __shfl_xor_sync(0xffffffffu, ps1, 2);
        l0 = l0 * a0s + ps0;
        l1 = l1 * a1s + ps1;
        m0 = mn0; m1 = mn1;

        #pragma unroll
        for (int nf = 0; nf < 8; nf++) {
            o[nf][0] *= a0s; o[nf][1] *= a0s;
            o[nf][2] *= a1s; o[nf][3] *= a1s;
        }
        __syncwarp();   // P rows are warp-private

        // ---- O += P @ V : A=P (k=kv), B[k][n]=V[kv][d]=Vst[d][kv] ----
        #pragma unroll
        for (int ks = 0; ks < 4; ks++) {
            const int k = ks * 16;
            uint32_t a0 = ldh2(Ps + r0l * PH_S + k + 2 * t4);
            uint32_t a1 = ldh2(Ps + (r0l + 8) * PH_S + k + 2 * t4);
            uint32_t a2 = ldh2(Ps + r0l * PH_S + k + 2 * t4 + 8);
            uint32_t a3 = ldh2(Ps + (r0l + 8) * PH_S + k + 2 * t4 + 8);
            #pragma unroll
            for (int nf = 0; nf < 8; nf++) {
                int cc = nf * 8 + g2;
                uint32_t b0 = ldh2(Vc + cc * VH_S + k + 2 * t4);
                uint32_t b1 = ldh2(Vc + cc * VH_S + k + 2 * t4 + 8);
                mma16(o[nf], a0, a1, a2, a3, b0, b1);
            }
        }
    }

    const float inv0 = 1.f / l0, inv1 = 1.f / l1;
    #pragma unroll
    for (int nf = 0; nf < 8; nf++) {
        int cc = nf * 8 + t4 * 2;
        __half* p0 = attn_out + (size_t)(b * SEQ + grow0) * HID + h * 64 + cc;
        __half* p1 = attn_out + (size_t)(b * SEQ + grow1) * HID + h * 64 + cc;
        *reinterpret_cast<__half2*>(p0) =
            __float22half2_rn(make_float2(o[nf][0] * inv0, o[nf][1] * inv0));
        *reinterpret_cast<__half2*>(p1) =
            __float22half2_rn(make_float2(o[nf][2] * inv1, o[nf][3] * inv1));
    }
}

// ---------------------------------------------------------------------------
extern "C" void kernel_launch(void* const* d_in, const int* in_sizes, int n_in,
                              void* d_out, int out_size)
{
    const float* x     = (const float*)d_in[0];
    const float* w_qkv = (const float*)d_in[1];
    const float* b_qkv = (const float*)d_in[2];
    const float* w_out = (const float*)d_in[3];
    const float* b_out = (const float*)d_in[4];
    float* out = (float*)d_out;

    __half *xh, *w1t, *w2t, *qkvh, *vt, *attnh;
    cudaGetSymbolAddress((void**)&xh,    g_xh);
    cudaGetSymbolAddress((void**)&w1t,   g_w1t);
    cudaGetSymbolAddress((void**)&w2t,   g_w2t);
    cudaGetSymbolAddress((void**)&qkvh,  g_qkvh);
    cudaGetSymbolAddress((void**)&vt,    g_vt);
    cudaGetSymbolAddress((void**)&attnh, g_attnh);

    cudaFuncSetAttribute(gemm_h,  cudaFuncAttributeMaxDynamicSharedMemorySize, GEMM_SMEM);
    cudaFuncSetAttribute(flash_h, cudaFuncAttributeMaxDynamicSharedMemorySize, FLASH_SMEM);

    // 0) prepasses: x -> fp16; weights -> fp16 transposed [N][K]
    conv_h_kernel<<<(NTOK * HID / 4 + 255) / 256, 256>>>(x, xh, NTOK * HID / 4);
    transpose_h_kernel<<<dim3(3 * HID / 32, HID / 32), 256>>>(w_qkv, w1t, HID, 3 * HID);
    transpose_h_kernel<<<dim3(HID / 32, HID / 32), 256>>>(w_out, w2t, HID, HID);

    // 1) qkv = x @ w_qkv + b_qkv  (fp16 out; V transposed)
    dim3 g1(3 * HID / 256, NTOK / 128);
    gemm_h<<<g1, 256, GEMM_SMEM>>>(xh, w1t, b_qkv, nullptr, qkvh, vt,
                                   NTOK, 3 * HID, HID, 1);

    // 2) causal flash attention (fp16)
    dim3 g2(SEQ / BQ, NHEAD, BATCH);
    flash_h<<<g2, 256, FLASH_SMEM>>>(qkvh, vt, attnh);

    // 3) out = attn @ w_out + b_out  (fp32 out)
    dim3 g3(HID / 256, NTOK / 128);
    gemm_h<<<g3, 256, GEMM_SMEM>>>(attnh, w2t, b_out, out, nullptr, nullptr,
                                   NTOK, HID, HID, 0);
}